// round 12
// baseline (speedup 1.0000x reference)
#include <cuda_runtime.h>
#include <cuda_bf16.h>
#include <cstdint>

#define NN 200000
#define NE 4000000
#define RR 4
#define DD 64
#define NRSEG (NN*RR)
#define GG 64
#define CC 10
#define ZN NN                            // sentinel node -> zero row
#define NES (NE + 3*NRSEG)               // padded edge-list capacity
#define SC_NB ((NRSEG + 1023) / 1024)    // 782 scan blocks
#define SGB ((NE + 1023) / 1024)         // 3907 scatter blocks
#define SLICE ((NRSEG + SGB - 1) / SGB)  // 205 offsets finalized per block
#define NW 61440                         // 3*5*4096 weight elems

// ---------------- device scratch (no allocations allowed) ----------------
static __device__ __align__(16) int   g_cntlook[NRSEG + 256]; // true counts
static __device__ __align__(16) int   g_off[NRSEG];    // padded per-block partial
static __device__ __align__(16) int   g_off2[NRSEG];   // padded finalized exclusive
static __device__ __align__(16) int   g_bsum[1024];
static __device__ __align__(16) int   g_rank[NE];
static __device__ __align__(16) int   g_sorted[NES];
static __device__ __align__(16) int   g_goff[GG + 1];
static __device__ __align__(16) __nv_bfloat16 g_hA[(NN + 1) * DD];
static __device__ __align__(16) __nv_bfloat16 g_hB[(NN + 1) * DD];
static __device__ __align__(16) __nv_bfloat16 g_M[RR * NN * DD]; // [r][node][64]
static __device__ __align__(16) __nv_bfloat16 g_Wb[NW];          // [l][c][k][e]
static __device__ __align__(16) float g_pp[GG * 4 * DD];

__device__ __forceinline__ void cpa16(uint32_t dst, const void* src, int srcsize) {
    asm volatile("cp.async.ca.shared.global [%0], [%1], 16, %2;"
                 :: "r"(dst), "l"(src), "r"(srcsize));
}

// ---------------- fused: hist(+rank) + h0 + zero rows + weight conversion --
__global__ void k_hist_h0(const int* __restrict__ tgt, const int* __restrict__ et,
                          const int* __restrict__ xop, const int* __restrict__ xcat,
                          const float* __restrict__ opemb, const float* __restrict__ catemb,
                          const float* __restrict__ w1, const float* __restrict__ r1,
                          const float* __restrict__ w2, const float* __restrict__ r2,
                          const float* __restrict__ w3, const float* __restrict__ r3) {
    int i = blockIdx.x * blockDim.x + threadIdx.x;
    if (i < NE) {
        int s = tgt[i] * RR + et[i];
        g_rank[i] = atomicAdd(&g_cntlook[s], 1);
        if (i < NW) { // weight conversion rides along (NW << NE)
            int l = i / 20480, r = i % 20480, c = r / 4096, j = r % 4096;
            const float* w = (l == 0) ? w1 : (l == 1) ? w2 : w3;
            const float* rt = (l == 0) ? r1 : (l == 1) ? r2 : r3;
            float v = (c < 4) ? w[c * 4096 + j] : rt[j];
            g_Wb[i] = __float2bfloat16(v);
        }
    }
    if (i < NN * 32) {
        int n = i >> 5, j = i & 31;
        const float2* oe = (const float2*)opemb;
        const float2* ce = (const float2*)catemb;
        float2 a = oe[xop[n] * 32 + j];
        float2 b = ce[xcat[n] * 32 + j];
        ((__nv_bfloat162*)g_hA)[n * 32 + j] =
            __float22bfloat162_rn(make_float2(a.x + b.x, a.y + b.y));
    } else if (i < NN * 32 + 64) {
        int j = i - NN * 32;
        __nv_bfloat162 z = __float2bfloat162_rn(0.f);
        if (j < 32) ((__nv_bfloat162*)g_hA)[NN * 32 + j] = z;
        else        ((__nv_bfloat162*)g_hB)[NN * 32 + (j - 32)] = z;
    }
}

// ---------------- block-local exclusive scan over PADDED counts -----------
__global__ void k_scan1() {
    __shared__ int sh[1024];
    int t = threadIdx.x;
    int i = blockIdx.x * 1024 + t;
    int v = 0;
    if (i < NRSEG) v = (g_cntlook[i] + 3) & ~3;   // pad to multiple of 4
    sh[t] = v;
    __syncthreads();
    for (int s = 1; s < 1024; s <<= 1) {
        int add = (t >= s) ? sh[t - s] : 0;
        __syncthreads();
        sh[t] += add;
        __syncthreads();
    }
    if (i < NRSEG) g_off[i] = sh[t] - v;
    if (t == 1023) g_bsum[blockIdx.x] = sh[1023];
}

// ---------------- fused: bsum-prefix + finalize + pad-fill + scatter + goff
__global__ __launch_bounds__(256) void k_scatter_goff(const int* __restrict__ srcarr,
                                                      const int* __restrict__ tgt,
                                                      const int* __restrict__ et,
                                                      const int* __restrict__ batch) {
    __shared__ int pre[1024];
    __shared__ int wsum[8];
    int b = blockIdx.x, t = threadIdx.x;
    int x[4];
    int run = 0;
#pragma unroll
    for (int k = 0; k < 4; ++k) {
        int i = t * 4 + k;
        int v = (i < SC_NB) ? g_bsum[i] : 0;
        x[k] = run;
        run += v;
    }
    int lane = t & 31, wp = t >> 5;
    int inc = run;
#pragma unroll
    for (int d = 1; d < 32; d <<= 1) {
        int y = __shfl_up_sync(0xffffffffu, inc, d);
        if (lane >= d) inc += y;
    }
    if (lane == 31) wsum[wp] = inc;
    __syncthreads();
    if (wp == 0) {
        int ws = (lane < 8) ? wsum[lane] : 0;
#pragma unroll
        for (int d = 1; d < 8; d <<= 1) {
            int y = __shfl_up_sync(0xffffffffu, ws, d);
            if (lane >= d) ws += y;
        }
        if (lane < 8) wsum[lane] = ws;
    }
    __syncthreads();
    int excl = inc - run + (wp > 0 ? wsum[wp - 1] : 0);
#pragma unroll
    for (int k = 0; k < 4; ++k) pre[t * 4 + k] = excl + x[k];
    __syncthreads();

    if (t < SLICE) {
        int i = b * SLICE + t;
        if (i < NRSEG) {
            int o = g_off[i] + pre[i >> 10];
            g_off2[i] = o;
            int c = g_cntlook[i];
            int pc = (c + 3) & ~3;
            for (int p = c; p < pc; ++p) g_sorted[o + p] = ZN;
        }
    }

#pragma unroll
    for (int k = 0; k < 4; ++k) {
        int e = b * 1024 + k * 256 + t;
        if (e < NE) {
            int s = tgt[e] * RR + et[e];
            g_sorted[g_off[s] + pre[s >> 10] + g_rank[e]] = srcarr[e];
        }
        if (e < NN) {
            int bb = batch[e];
            if (e == 0) {
                for (int g = 0; g <= bb; ++g) g_goff[g] = 0;
            } else {
                int bp = batch[e - 1];
                for (int g = bp + 1; g <= bb; ++g) g_goff[g] = e;
            }
            if (e == NN - 1) {
                for (int g = bb + 1; g <= GG; ++g) g_goff[g] = NN;
            }
        }
    }
}

// ---------------- per-(node,relation) mean aggregation v5 ------------------
__global__ __launch_bounds__(256) void k_agg(int inB) {
    int gw = (blockIdx.x * blockDim.x + threadIdx.x) >> 5;
    int lane = threadIdx.x & 31;
    if (gw >= NN) return;
    int q = lane & 7;
    int g = lane >> 3;
    const __nv_bfloat16* hin = inB ? g_hB : g_hA;

    int off_g = g_off2[gw * RR + g];      // 8-lane broadcast load
    int cnt_g = g_cntlook[gw * RR + g];   // 8-lane broadcast load
    int iters_g = (cnt_g + 3) >> 2;
    int im = iters_g;
    im = max(im, __shfl_xor_sync(0xffffffffu, im, 8));
    im = max(im, __shfl_xor_sync(0xffffffffu, im, 16));

    __nv_bfloat162 a0 = __float2bfloat162_rn(0.f);
    __nv_bfloat162 a1 = a0, a2 = a0, a3 = a0;

    const int4* ip = (const int4*)(g_sorted + off_g);  // off_g % 4 == 0
    const int4 zf = make_int4(ZN, ZN, ZN, ZN);
    int4 i4 = (0 < iters_g) ? ip[0] : zf;
    for (int it = 0; it < im; ++it) {
        int4 nxt = ((it + 1) < iters_g) ? ip[it + 1] : zf;
#pragma unroll
        for (int t = 0; t < 4; ++t) {
            int sn = (t == 0) ? i4.x : (t == 1) ? i4.y : (t == 2) ? i4.z : i4.w;
            uint4 v = *(const uint4*)(hin + sn * 64 + q * 8);
            a0 = __hadd2(a0, *(const __nv_bfloat162*)&v.x);
            a1 = __hadd2(a1, *(const __nv_bfloat162*)&v.y);
            a2 = __hadd2(a2, *(const __nv_bfloat162*)&v.z);
            a3 = __hadd2(a3, *(const __nv_bfloat162*)&v.w);
        }
        i4 = nxt;
    }

    float inv = (cnt_g > 0) ? (1.f / (float)cnt_g) : 0.f;
    __nv_bfloat162 o[4];
    float2 f;
    f = __bfloat1622float2(a0); o[0] = __float22bfloat162_rn(make_float2(f.x * inv, f.y * inv));
    f = __bfloat1622float2(a1); o[1] = __float22bfloat162_rn(make_float2(f.x * inv, f.y * inv));
    f = __bfloat1622float2(a2); o[2] = __float22bfloat162_rn(make_float2(f.x * inv, f.y * inv));
    f = __bfloat1622float2(a3); o[3] = __float22bfloat162_rn(make_float2(f.x * inv, f.y * inv));
    *(uint4*)(g_M + (g * NN + gw) * 64 + q * 8) = *(const uint4*)o;
}

// ---------------- mma.sync GEMM v3: occupancy-first --------------------
// tile 128 nodes x 64 outputs, K = 10 chunks of 32, double-buffered cp.async.
// 32 accumulators/thread, static smem 25.9KB, 4 CTAs/SM target.
// Smem row stride 40 elems (80B): r*80 mod 128 cycles 8 distinct 16B banks.
#define ASTR 40
#define A_ELEM (128 * ASTR)   // 5120 elems, 10240 B
#define B_ELEM (32 * ASTR)    // 1280 elems, 2560 B
__global__ __launch_bounds__(256, 4) void k_gemm(int inB, int l,
                                                 const float* __restrict__ bias,
                                                 int do_relu) {
    __shared__ __nv_bfloat16 As[2][A_ELEM];
    __shared__ __nv_bfloat16 Bs[2][B_ELEM];
    __shared__ float biass[64];

    const __nv_bfloat16* hin = inB ? g_hB : g_hA;
    __nv_bfloat16* hout = inB ? g_hA : g_hB;
    const __nv_bfloat16* wb = g_Wb + l * 20480;

    int tid = threadIdx.x;
    int lane = tid & 31;
    int wp = tid >> 5;
    int nbase = blockIdx.x * 128;

    if (tid < 64) biass[tid] = bias[tid];

    float d[4][2][4];
#pragma unroll
    for (int t = 0; t < 4; ++t)
#pragma unroll
        for (int s = 0; s < 2; ++s)
#pragma unroll
            for (int i = 0; i < 4; ++i) d[t][s][i] = 0.f;

    uint32_t as_base = (uint32_t)__cvta_generic_to_shared(&As[0][0]);
    uint32_t bs_base = (uint32_t)__cvta_generic_to_shared(&Bs[0][0]);

    // chunk c (0..9): K rows [c*32, c*32+32) of the K=320 concat.
    // c<8: relation c>>1, k-half c&1 of g_M; c>=8: k-half c-8 of h.
    auto stage = [&](int c, int buf) {
        // B: 32 k-rows x 64 e = 256 x 16B granules, 1/thread
        {
            int kk = tid >> 3, e8 = tid & 7;
            const __nv_bfloat16* src = wb + (c >> 1) * 4096 + ((c & 1) * 32 + kk) * 64 + e8 * 8;
            cpa16(bs_base + (buf * B_ELEM + kk * ASTR + e8 * 8) * 2, src, 16);
        }
        // A: 128 nodes x 32 k = 512 x 16B granules, 2/thread
#pragma unroll
        for (int it = 0; it < 2; ++it) {
            int idx = it * 256 + tid;
            int node = idx >> 2, k8 = idx & 3;
            int gn = nbase + node;
            int gs = gn < NN ? gn : NN - 1;
            const __nv_bfloat16* src = (c < 8)
                ? (g_M + ((c >> 1) * NN + gs) * 64 + (c & 1) * 32 + k8 * 8)
                : (hin + gs * 64 + (c - 8) * 32 + k8 * 8);
            cpa16(as_base + (buf * A_ELEM + node * ASTR + k8 * 8) * 2, src,
                  gn < NN ? 16 : 0);
        }
    };

    stage(0, 0);
    asm volatile("cp.async.commit_group;");

    for (int c = 0; c < 10; ++c) {
        int buf = c & 1;
        if (c < 9) {
            stage(c + 1, (c + 1) & 1);
            asm volatile("cp.async.commit_group;");
            asm volatile("cp.async.wait_group 1;");
        } else {
            asm volatile("cp.async.wait_group 0;");
        }
        __syncthreads();

        uint32_t ab = as_base + buf * A_ELEM * 2;
        uint32_t bb = bs_base + buf * B_ELEM * 2;
#pragma unroll
        for (int ks = 0; ks < 2; ++ks) {
            uint32_t a0, a1, a2, a3;
            uint32_t aaddr = ab +
                ((wp * 16 + (lane & 15)) * ASTR + ks * 16 + ((lane >> 4) << 3)) * 2;
            asm volatile(
                "ldmatrix.sync.aligned.m8n8.x4.shared.b16 {%0,%1,%2,%3}, [%4];"
                : "=r"(a0), "=r"(a1), "=r"(a2), "=r"(a3) : "r"(aaddr));
#pragma unroll
            for (int t = 0; t < 4; ++t) {
                uint32_t b0, b1, b2, b3;
                uint32_t baddr = bb +
                    ((ks * 16 + (lane & 15)) * ASTR + t * 16 + ((lane >> 4) << 3)) * 2;
                asm volatile(
                    "ldmatrix.sync.aligned.m8n8.x4.trans.shared.b16 {%0,%1,%2,%3}, [%4];"
                    : "=r"(b0), "=r"(b1), "=r"(b2), "=r"(b3) : "r"(baddr));
                asm volatile(
                    "mma.sync.aligned.m16n8k16.row.col.f32.bf16.bf16.f32 "
                    "{%0,%1,%2,%3}, {%4,%5,%6,%7}, {%8,%9}, {%0,%1,%2,%3};"
                    : "+f"(d[t][0][0]), "+f"(d[t][0][1]), "+f"(d[t][0][2]), "+f"(d[t][0][3])
                    : "r"(a0), "r"(a1), "r"(a2), "r"(a3), "r"(b0), "r"(b1));
                asm volatile(
                    "mma.sync.aligned.m16n8k16.row.col.f32.bf16.bf16.f32 "
                    "{%0,%1,%2,%3}, {%4,%5,%6,%7}, {%8,%9}, {%0,%1,%2,%3};"
                    : "+f"(d[t][1][0]), "+f"(d[t][1][1]), "+f"(d[t][1][2]), "+f"(d[t][1][3])
                    : "r"(a0), "r"(a1), "r"(a2), "r"(a3), "r"(b2), "r"(b3));
            }
        }
        __syncthreads();
    }

    // epilogue: bias + relu, bf16 store
    int r0 = nbase + wp * 16 + (lane >> 2);
    int r1 = r0 + 8;
    __nv_bfloat162* hout2 = (__nv_bfloat162*)hout;
#pragma unroll
    for (int t = 0; t < 4; ++t) {
#pragma unroll
        for (int s = 0; s < 2; ++s) {
            int n0 = t * 16 + s * 8 + (lane & 3) * 2;
            float bx = biass[n0], by = biass[n0 + 1];
            float v0 = d[t][s][0] + bx, v1 = d[t][s][1] + by;
            float v2 = d[t][s][2] + bx, v3 = d[t][s][3] + by;
            if (do_relu) {
                v0 = fmaxf(v0, 0.f); v1 = fmaxf(v1, 0.f);
                v2 = fmaxf(v2, 0.f); v3 = fmaxf(v3, 0.f);
            }
            if (r0 < NN)
                hout2[r0 * 32 + n0 / 2] = __float22bfloat162_rn(make_float2(v0, v1));
            if (r1 < NN)
                hout2[r1 * 32 + n0 / 2] = __float22bfloat162_rn(make_float2(v2, v3));
        }
    }
}

// ---------------- pooling: (graph, quarter) partial sums -------------------
__global__ void k_pool(int inB) {
    const __nv_bfloat16* h = inB ? g_hB : g_hA;
    int g = blockIdx.x, qt = blockIdx.y;
    int st = g_goff[g], en = g_goff[g + 1];
    int len = en - st;
    int n0 = st + (len * qt) / 4;
    int n1 = st + (len * (qt + 1)) / 4;
    int d = threadIdx.x & 63;
    int y = threadIdx.x >> 6;
    float acc = 0.f;
    for (int n = n0 + y; n < n1; n += 4) acc += __bfloat162float(h[n * DD + d]);
    __shared__ float red[4][64];
    red[y][d] = acc;
    __syncthreads();
    if (y == 0)
        g_pp[(g * 4 + qt) * DD + d] = red[0][d] + red[1][d] + red[2][d] + red[3][d];
}

// ---------------- MLP head + log_softmax ------------------------------------
__global__ void k_head(const float* __restrict__ fc1w, const float* __restrict__ fc1b,
                       const float* __restrict__ fc2w, const float* __restrict__ fc2b,
                       float* __restrict__ out) {
    __shared__ float w1s[DD * DD];
    __shared__ float w2s[DD * CC];
    __shared__ float b1s[DD];
    __shared__ float b2s[CC];
    int t = threadIdx.x; // 64 threads
    for (int i = t; i < DD * DD; i += 64) w1s[i] = fc1w[i];
    for (int i = t; i < DD * CC; i += 64) w2s[i] = fc2w[i];
    if (t < DD) b1s[t] = fc1b[t];
    if (t < CC) b2s[t] = fc2b[t];
    __syncthreads();
    int g = t;
    int cnt = g_goff[g + 1] - g_goff[g];
    float inv = 1.f / (float)(cnt > 0 ? cnt : 1);
    float p[DD];
#pragma unroll
    for (int d = 0; d < DD; ++d)
        p[d] = (g_pp[(g * 4 + 0) * DD + d] + g_pp[(g * 4 + 1) * DD + d] +
                g_pp[(g * 4 + 2) * DD + d] + g_pp[(g * 4 + 3) * DD + d]) * inv;
    float t1[DD];
    for (int e = 0; e < DD; ++e) {
        float a = b1s[e];
#pragma unroll
        for (int d = 0; d < DD; ++d) a += p[d] * w1s[d * DD + e];
        t1[e] = fmaxf(a, 0.f);
    }
    float lg[CC];
    for (int c = 0; c < CC; ++c) {
        float a = b2s[c];
#pragma unroll
        for (int e = 0; e < DD; ++e) a += t1[e] * w2s[e * CC + c];
        lg[c] = a;
    }
    float m = lg[0];
    for (int c = 1; c < CC; ++c) m = fmaxf(m, lg[c]);
    float s = 0.f;
    for (int c = 0; c < CC; ++c) s += expf(lg[c] - m);
    float ls = logf(s);
    for (int c = 0; c < CC; ++c) out[g * CC + c] = lg[c] - m - ls;
}

// ---------------- launch --------------------------------------------------
extern "C" void kernel_launch(void* const* d_in, const int* in_sizes, int n_in,
                              void* d_out, int out_size) {
    const int* x_op = (const int*)d_in[0];
    const int* x_cat = (const int*)d_in[1];
    const int* ei = (const int*)d_in[2];
    const int* etyp = (const int*)d_in[3];
    const int* batch = (const int*)d_in[4];
    const float* opemb = (const float*)d_in[5];
    const float* catemb = (const float*)d_in[6];
    const float* W[3] = {(const float*)d_in[7], (const float*)d_in[10], (const float*)d_in[13]};
    const float* Rt[3] = {(const float*)d_in[8], (const float*)d_in[11], (const float*)d_in[14]};
    const float* Bi[3] = {(const float*)d_in[9], (const float*)d_in[12], (const float*)d_in[15]};
    const float* fc1w = (const float*)d_in[16];
    const float* fc1b = (const float*)d_in[17];
    const float* fc2w = (const float*)d_in[18];
    const float* fc2b = (const float*)d_in[19];
    float* out = (float*)d_out;
    const int* src = ei;
    const int* tgt = ei + NE;

    // zero counts via memset node
    void* cl_ptr = nullptr;
    cudaGetSymbolAddress(&cl_ptr, g_cntlook);
    cudaMemsetAsync(cl_ptr, 0, (NRSEG + 256) * sizeof(int), 0);

    k_hist_h0<<<(NN * 32 + 64 + 255) / 256, 256>>>(tgt, etyp, x_op, x_cat, opemb, catemb,
                                                   W[0], Rt[0], W[1], Rt[1], W[2], Rt[2]);
    k_scan1<<<SC_NB, 1024>>>();
    k_scatter_goff<<<SGB, 256>>>(src, tgt, etyp, batch);

    // 3 RGCN layers, ping-pong hA/hB
    for (int l = 0; l < 3; ++l) {
        int inB = l & 1;
        k_agg<<<(NN * 32 + 255) / 256, 256>>>(inB);
        k_gemm<<<(NN + 127) / 128, 256>>>(inB, l, Bi[l], (l < 2) ? 1 : 0);
    }

    k_pool<<<dim3(GG, 4), 256>>>(1); // final h is in g_hB
    k_head<<<1, 64>>>(fc1w, fc1b, fc2w, fc2b, out);
}

// round 14
// speedup vs baseline: 1.2885x; 1.2885x over previous
#include <cuda_runtime.h>
#include <cuda_bf16.h>
#include <cstdint>

#define NN 200000
#define NE 4000000
#define RR 4
#define DD 64
#define NRSEG (NN*RR)
#define GG 64
#define CC 10
#define ZN NN                            // sentinel node -> zero row
#define NES (NE + 3*NRSEG)               // padded edge-list capacity
#define SC_NB ((NRSEG + 1023) / 1024)    // 782 scan blocks
#define SGB ((NE + 1023) / 1024)         // 3907 scatter blocks
#define SLICE ((NRSEG + SGB - 1) / SGB)  // 205 offsets finalized per block
#define NW 61440                         // 3*5*4096 weight elems

// ---------------- device scratch (no allocations allowed) ----------------
static __device__ __align__(16) int   g_cntlook[NRSEG + 256]; // true counts
static __device__ __align__(16) int   g_off[NRSEG];    // padded per-block partial
static __device__ __align__(16) int   g_off2[NRSEG];   // padded finalized exclusive
static __device__ __align__(16) int   g_bsum[1024];
static __device__ __align__(16) int   g_rank[NE];
static __device__ __align__(16) int   g_sorted[NES];
static __device__ __align__(16) int   g_goff[GG + 1];
static __device__ __align__(16) __nv_bfloat16 g_hA[(NN + 1) * DD];
static __device__ __align__(16) __nv_bfloat16 g_hB[(NN + 1) * DD];
static __device__ __align__(16) __nv_bfloat16 g_M[RR * NN * DD]; // [r][node][64]
static __device__ __align__(16) __nv_bfloat16 g_Wb[NW];          // [l][c][k][e]
static __device__ __align__(16) float g_pp[GG * 4 * DD];

__device__ __forceinline__ void cpa16(uint32_t dst, const void* src, int srcsize) {
    asm volatile("cp.async.ca.shared.global [%0], [%1], 16, %2;"
                 :: "r"(dst), "l"(src), "r"(srcsize));
}

// ---------------- fused: hist(+rank, int4 edges) + h0 + zero + weights -----
__global__ void k_hist_h0(const int* __restrict__ tgt, const int* __restrict__ et,
                          const int* __restrict__ xop, const int* __restrict__ xcat,
                          const float* __restrict__ opemb, const float* __restrict__ catemb,
                          const float* __restrict__ w1, const float* __restrict__ r1,
                          const float* __restrict__ w2, const float* __restrict__ r2,
                          const float* __restrict__ w3, const float* __restrict__ r3) {
    int i = blockIdx.x * blockDim.x + threadIdx.x;
    if (i < NE / 4) {   // 4 edges per thread, vectorized streams
        int4 t4 = ((const int4*)tgt)[i];
        int4 e4 = ((const int4*)et)[i];
        int4 r4;
        r4.x = atomicAdd(&g_cntlook[t4.x * RR + e4.x], 1);
        r4.y = atomicAdd(&g_cntlook[t4.y * RR + e4.y], 1);
        r4.z = atomicAdd(&g_cntlook[t4.z * RR + e4.z], 1);
        r4.w = atomicAdd(&g_cntlook[t4.w * RR + e4.w], 1);
        ((int4*)g_rank)[i] = r4;
        if (i < NW) { // weight conversion rides along
            int l = i / 20480, r = i % 20480, c = r / 4096, j = r % 4096;
            const float* w = (l == 0) ? w1 : (l == 1) ? w2 : w3;
            const float* rt = (l == 0) ? r1 : (l == 1) ? r2 : r3;
            float v = (c < 4) ? w[c * 4096 + j] : rt[j];
            g_Wb[i] = __float2bfloat16(v);
        }
    }
    if (i < NN * 32) {
        int n = i >> 5, j = i & 31;
        const float2* oe = (const float2*)opemb;
        const float2* ce = (const float2*)catemb;
        float2 a = oe[xop[n] * 32 + j];
        float2 b = ce[xcat[n] * 32 + j];
        ((__nv_bfloat162*)g_hA)[n * 32 + j] =
            __float22bfloat162_rn(make_float2(a.x + b.x, a.y + b.y));
    } else if (i < NN * 32 + 64) {
        int j = i - NN * 32;
        __nv_bfloat162 z = __float2bfloat162_rn(0.f);
        if (j < 32) ((__nv_bfloat162*)g_hA)[NN * 32 + j] = z;
        else        ((__nv_bfloat162*)g_hB)[NN * 32 + (j - 32)] = z;
    }
}

// ---------------- block-local exclusive scan over PADDED counts -----------
__global__ void k_scan1() {
    __shared__ int sh[1024];
    int t = threadIdx.x;
    int i = blockIdx.x * 1024 + t;
    int v = 0;
    if (i < NRSEG) v = (g_cntlook[i] + 3) & ~3;   // pad to multiple of 4
    sh[t] = v;
    __syncthreads();
    for (int s = 1; s < 1024; s <<= 1) {
        int add = (t >= s) ? sh[t - s] : 0;
        __syncthreads();
        sh[t] += add;
        __syncthreads();
    }
    if (i < NRSEG) g_off[i] = sh[t] - v;
    if (t == 1023) g_bsum[blockIdx.x] = sh[1023];
}

// ---------------- fused: bsum-prefix + finalize + pad-fill + scatter + goff
__global__ __launch_bounds__(256) void k_scatter_goff(const int* __restrict__ srcarr,
                                                      const int* __restrict__ tgt,
                                                      const int* __restrict__ et,
                                                      const int* __restrict__ batch) {
    __shared__ int pre[1024];
    __shared__ int wsum[8];
    int b = blockIdx.x, t = threadIdx.x;
    int x[4];
    int run = 0;
#pragma unroll
    for (int k = 0; k < 4; ++k) {
        int i = t * 4 + k;
        int v = (i < SC_NB) ? g_bsum[i] : 0;
        x[k] = run;
        run += v;
    }
    int lane = t & 31, wp = t >> 5;
    int inc = run;
#pragma unroll
    for (int d = 1; d < 32; d <<= 1) {
        int y = __shfl_up_sync(0xffffffffu, inc, d);
        if (lane >= d) inc += y;
    }
    if (lane == 31) wsum[wp] = inc;
    __syncthreads();
    if (wp == 0) {
        int ws = (lane < 8) ? wsum[lane] : 0;
#pragma unroll
        for (int d = 1; d < 8; d <<= 1) {
            int y = __shfl_up_sync(0xffffffffu, ws, d);
            if (lane >= d) ws += y;
        }
        if (lane < 8) wsum[lane] = ws;
    }
    __syncthreads();
    int excl = inc - run + (wp > 0 ? wsum[wp - 1] : 0);
#pragma unroll
    for (int k = 0; k < 4; ++k) pre[t * 4 + k] = excl + x[k];
    __syncthreads();

    // finalize slice of padded offsets + fill pad slots with sentinel ZN
    if (t < SLICE) {
        int i = b * SLICE + t;
        if (i < NRSEG) {
            int o = g_off[i] + pre[i >> 10];
            g_off2[i] = o;
            int c = g_cntlook[i];
            int pc = (c + 3) & ~3;
            for (int p = c; p < pc; ++p) g_sorted[o + p] = ZN;
        }
    }

    // atomic-free scatter, 4 edges/thread via int4 streams + batch boundaries
    {
        int gi = b * 256 + t;               // int4 index; 4 edges
        if (gi < NE / 4) {
            int4 t4 = ((const int4*)tgt)[gi];
            int4 e4 = ((const int4*)et)[gi];
            int4 s4 = ((const int4*)srcarr)[gi];
            int4 r4 = ((const int4*)g_rank)[gi];
            int s;
            s = t4.x * RR + e4.x; g_sorted[g_off[s] + pre[s >> 10] + r4.x] = s4.x;
            s = t4.y * RR + e4.y; g_sorted[g_off[s] + pre[s >> 10] + r4.y] = s4.y;
            s = t4.z * RR + e4.z; g_sorted[g_off[s] + pre[s >> 10] + r4.z] = s4.z;
            s = t4.w * RR + e4.w; g_sorted[g_off[s] + pre[s >> 10] + r4.w] = s4.w;
        }
#pragma unroll
        for (int k = 0; k < 4; ++k) {
            int e = gi * 4 + k;
            if (e < NN) {
                int bb = batch[e];
                if (e == 0) {
                    for (int g = 0; g <= bb; ++g) g_goff[g] = 0;
                } else {
                    int bp = batch[e - 1];
                    for (int g = bp + 1; g <= bb; ++g) g_goff[g] = e;
                }
                if (e == NN - 1) {
                    for (int g = bb + 1; g <= GG; ++g) g_goff[g] = NN;
                }
            }
        }
    }
}

// ---------------- per-(node,relation) mean aggregation v5 ------------------
__global__ __launch_bounds__(256) void k_agg(int inB) {
    int gw = (blockIdx.x * blockDim.x + threadIdx.x) >> 5;
    int lane = threadIdx.x & 31;
    if (gw >= NN) return;
    int q = lane & 7;
    int g = lane >> 3;
    const __nv_bfloat16* hin = inB ? g_hB : g_hA;

    int off_g = g_off2[gw * RR + g];      // 8-lane broadcast load
    int cnt_g = g_cntlook[gw * RR + g];   // 8-lane broadcast load
    int iters_g = (cnt_g + 3) >> 2;
    int im = iters_g;
    im = max(im, __shfl_xor_sync(0xffffffffu, im, 8));
    im = max(im, __shfl_xor_sync(0xffffffffu, im, 16));

    __nv_bfloat162 a0 = __float2bfloat162_rn(0.f);
    __nv_bfloat162 a1 = a0, a2 = a0, a3 = a0;

    const int4* ip = (const int4*)(g_sorted + off_g);  // off_g % 4 == 0
    const int4 zf = make_int4(ZN, ZN, ZN, ZN);
    int4 i4 = (0 < iters_g) ? ip[0] : zf;
    for (int it = 0; it < im; ++it) {
        int4 nxt = ((it + 1) < iters_g) ? ip[it + 1] : zf;
#pragma unroll
        for (int t = 0; t < 4; ++t) {
            int sn = (t == 0) ? i4.x : (t == 1) ? i4.y : (t == 2) ? i4.z : i4.w;
            uint4 v = *(const uint4*)(hin + sn * 64 + q * 8);
            a0 = __hadd2(a0, *(const __nv_bfloat162*)&v.x);
            a1 = __hadd2(a1, *(const __nv_bfloat162*)&v.y);
            a2 = __hadd2(a2, *(const __nv_bfloat162*)&v.z);
            a3 = __hadd2(a3, *(const __nv_bfloat162*)&v.w);
        }
        i4 = nxt;
    }

    float inv = (cnt_g > 0) ? (1.f / (float)cnt_g) : 0.f;
    __nv_bfloat162 o[4];
    float2 f;
    f = __bfloat1622float2(a0); o[0] = __float22bfloat162_rn(make_float2(f.x * inv, f.y * inv));
    f = __bfloat1622float2(a1); o[1] = __float22bfloat162_rn(make_float2(f.x * inv, f.y * inv));
    f = __bfloat1622float2(a2); o[2] = __float22bfloat162_rn(make_float2(f.x * inv, f.y * inv));
    f = __bfloat1622float2(a3); o[3] = __float22bfloat162_rn(make_float2(f.x * inv, f.y * inv));
    *(uint4*)(g_M + (g * NN + gw) * 64 + q * 8) = *(const uint4*)o;
}

// ---------------- mma.sync GEMM (R10 structure, M-tile 128, 4 CTAs/SM) -----
// tile 128 nodes x 64 outputs, K = 5 chunks of 64, double-buffered cp.async.
// Identical inner loop / accumulation order to R10; only the node tile halved.
#define ASTR 72
#define A_ELEM (128 * ASTR)
#define B_ELEM (64 * ASTR)
#define GEMM_SMEM (2 * A_ELEM * 2 + 2 * B_ELEM * 2 + 256)
__global__ __launch_bounds__(256, 4) void k_gemm(int inB, int l,
                                                 const float* __restrict__ bias,
                                                 int do_relu) {
    extern __shared__ __align__(16) unsigned char dsm[];
    __nv_bfloat16* As = (__nv_bfloat16*)dsm;
    __nv_bfloat16* Bs = (__nv_bfloat16*)(dsm + 2 * A_ELEM * 2);
    float* biass = (float*)(dsm + 2 * A_ELEM * 2 + 2 * B_ELEM * 2);

    const __nv_bfloat16* hin = inB ? g_hB : g_hA;
    __nv_bfloat16* hout = inB ? g_hA : g_hB;
    const __nv_bfloat16* wb = g_Wb + l * 20480;

    int tid = threadIdx.x;
    int lane = tid & 31;
    int wp = tid >> 5;
    int nbase = blockIdx.x * 128;

    if (tid < 64) biass[tid] = bias[tid];

    float d[4][2][4];
#pragma unroll
    for (int t = 0; t < 4; ++t)
#pragma unroll
        for (int s = 0; s < 2; ++s)
#pragma unroll
            for (int i = 0; i < 4; ++i) d[t][s][i] = 0.f;

    uint32_t as_base = (uint32_t)__cvta_generic_to_shared(As);
    uint32_t bs_base = (uint32_t)__cvta_generic_to_shared(Bs);

    auto stage = [&](int c, int buf) {
#pragma unroll
        for (int it = 0; it < 2; ++it) {      // B: 64x64 bf16 = 512 x 16B
            int idx = it * 256 + tid;
            int kk = idx >> 3, e8 = idx & 7;
            uint32_t dst = bs_base + (buf * B_ELEM + kk * ASTR + e8 * 8) * 2;
            cpa16(dst, wb + c * 4096 + kk * 64 + e8 * 8, 16);
        }
#pragma unroll
        for (int it = 0; it < 4; ++it) {      // A: 128x64 bf16 = 1024 x 16B
            int idx = it * 256 + tid;
            int node = idx >> 3, k8 = idx & 7;
            int gn = nbase + node;
            int gs = gn < NN ? gn : NN - 1;
            const __nv_bfloat16* src = (c < 4) ? (g_M + (c * NN + gs) * 64 + k8 * 8)
                                               : (hin + gs * 64 + k8 * 8);
            uint32_t dst = as_base + (buf * A_ELEM + node * ASTR + k8 * 8) * 2;
            cpa16(dst, src, gn < NN ? 16 : 0);
        }
    };

    stage(0, 0);
    asm volatile("cp.async.commit_group;");

    for (int c = 0; c < 5; ++c) {
        int buf = c & 1;
        if (c < 4) {
            stage(c + 1, (c + 1) & 1);
            asm volatile("cp.async.commit_group;");
            asm volatile("cp.async.wait_group 1;");
        } else {
            asm volatile("cp.async.wait_group 0;");
        }
        __syncthreads();

        uint32_t ab = as_base + buf * A_ELEM * 2;
        uint32_t bb = bs_base + buf * B_ELEM * 2;
#pragma unroll
        for (int ks = 0; ks < 4; ++ks) {
            uint32_t a0, a1, a2, a3;
            uint32_t aaddr = ab +
                ((wp * 16 + (lane & 15)) * ASTR + ks * 16 + ((lane >> 4) << 3)) * 2;
            asm volatile(
                "ldmatrix.sync.aligned.m8n8.x4.shared.b16 {%0,%1,%2,%3}, [%4];"
                : "=r"(a0), "=r"(a1), "=r"(a2), "=r"(a3) : "r"(aaddr));
#pragma unroll
            for (int t = 0; t < 4; ++t) {
                uint32_t b0, b1, b2, b3;
                uint32_t baddr = bb +
                    ((ks * 16 + (lane & 15)) * ASTR + t * 16 + ((lane >> 4) << 3)) * 2;
                asm volatile(
                    "ldmatrix.sync.aligned.m8n8.x4.trans.shared.b16 {%0,%1,%2,%3}, [%4];"
                    : "=r"(b0), "=r"(b1), "=r"(b2), "=r"(b3) : "r"(baddr));
                asm volatile(
                    "mma.sync.aligned.m16n8k16.row.col.f32.bf16.bf16.f32 "
                    "{%0,%1,%2,%3}, {%4,%5,%6,%7}, {%8,%9}, {%0,%1,%2,%3};"
                    : "+f"(d[t][0][0]), "+f"(d[t][0][1]), "+f"(d[t][0][2]), "+f"(d[t][0][3])
                    : "r"(a0), "r"(a1), "r"(a2), "r"(a3), "r"(b0), "r"(b1));
                asm volatile(
                    "mma.sync.aligned.m16n8k16.row.col.f32.bf16.bf16.f32 "
                    "{%0,%1,%2,%3}, {%4,%5,%6,%7}, {%8,%9}, {%0,%1,%2,%3};"
                    : "+f"(d[t][1][0]), "+f"(d[t][1][1]), "+f"(d[t][1][2]), "+f"(d[t][1][3])
                    : "r"(a0), "r"(a1), "r"(a2), "r"(a3), "r"(b2), "r"(b3));
            }
        }
        __syncthreads();
    }

    // epilogue: bias + relu, bf16 store
    int r0 = nbase + wp * 16 + (lane >> 2);
    int r1 = r0 + 8;
    __nv_bfloat162* hout2 = (__nv_bfloat162*)hout;
#pragma unroll
    for (int t = 0; t < 4; ++t) {
#pragma unroll
        for (int s = 0; s < 2; ++s) {
            int n0 = t * 16 + s * 8 + (lane & 3) * 2;
            float bx = biass[n0], by = biass[n0 + 1];
            float v0 = d[t][s][0] + bx, v1 = d[t][s][1] + by;
            float v2 = d[t][s][2] + bx, v3 = d[t][s][3] + by;
            if (do_relu) {
                v0 = fmaxf(v0, 0.f); v1 = fmaxf(v1, 0.f);
                v2 = fmaxf(v2, 0.f); v3 = fmaxf(v3, 0.f);
            }
            if (r0 < NN)
                hout2[r0 * 32 + n0 / 2] = __float22bfloat162_rn(make_float2(v0, v1));
            if (r1 < NN)
                hout2[r1 * 32 + n0 / 2] = __float22bfloat162_rn(make_float2(v2, v3));
        }
    }
}

// ---------------- pooling: (graph, quarter) partial sums -------------------
__global__ void k_pool(int inB) {
    const __nv_bfloat16* h = inB ? g_hB : g_hA;
    int g = blockIdx.x, qt = blockIdx.y;
    int st = g_goff[g], en = g_goff[g + 1];
    int len = en - st;
    int n0 = st + (len * qt) / 4;
    int n1 = st + (len * (qt + 1)) / 4;
    int d = threadIdx.x & 63;
    int y = threadIdx.x >> 6;
    float acc = 0.f;
    for (int n = n0 + y; n < n1; n += 4) acc += __bfloat162float(h[n * DD + d]);
    __shared__ float red[4][64];
    red[y][d] = acc;
    __syncthreads();
    if (y == 0)
        g_pp[(g * 4 + qt) * DD + d] = red[0][d] + red[1][d] + red[2][d] + red[3][d];
}

// ---------------- MLP head + log_softmax ------------------------------------
__global__ void k_head(const float* __restrict__ fc1w, const float* __restrict__ fc1b,
                       const float* __restrict__ fc2w, const float* __restrict__ fc2b,
                       float* __restrict__ out) {
    __shared__ float w1s[DD * DD];
    __shared__ float w2s[DD * CC];
    __shared__ float b1s[DD];
    __shared__ float b2s[CC];
    int t = threadIdx.x; // 64 threads
    for (int i = t; i < DD * DD; i += 64) w1s[i] = fc1w[i];
    for (int i = t; i < DD * CC; i += 64) w2s[i] = fc2w[i];
    if (t < DD) b1s[t] = fc1b[t];
    if (t < CC) b2s[t] = fc2b[t];
    __syncthreads();
    int g = t;
    int cnt = g_goff[g + 1] - g_goff[g];
    float inv = 1.f / (float)(cnt > 0 ? cnt : 1);
    float p[DD];
#pragma unroll
    for (int d = 0; d < DD; ++d)
        p[d] = (g_pp[(g * 4 + 0) * DD + d] + g_pp[(g * 4 + 1) * DD + d] +
                g_pp[(g * 4 + 2) * DD + d] + g_pp[(g * 4 + 3) * DD + d]) * inv;
    float t1[DD];
    for (int e = 0; e < DD; ++e) {
        float a = b1s[e];
#pragma unroll
        for (int d = 0; d < DD; ++d) a += p[d] * w1s[d * DD + e];
        t1[e] = fmaxf(a, 0.f);
    }
    float lg[CC];
    for (int c = 0; c < CC; ++c) {
        float a = b2s[c];
#pragma unroll
        for (int e = 0; e < DD; ++e) a += t1[e] * w2s[e * CC + c];
        lg[c] = a;
    }
    float m = lg[0];
    for (int c = 1; c < CC; ++c) m = fmaxf(m, lg[c]);
    float s = 0.f;
    for (int c = 0; c < CC; ++c) s += expf(lg[c] - m);
    float ls = logf(s);
    for (int c = 0; c < CC; ++c) out[g * CC + c] = lg[c] - m - ls;
}

// ---------------- launch --------------------------------------------------
extern "C" void kernel_launch(void* const* d_in, const int* in_sizes, int n_in,
                              void* d_out, int out_size) {
    const int* x_op = (const int*)d_in[0];
    const int* x_cat = (const int*)d_in[1];
    const int* ei = (const int*)d_in[2];
    const int* etyp = (const int*)d_in[3];
    const int* batch = (const int*)d_in[4];
    const float* opemb = (const float*)d_in[5];
    const float* catemb = (const float*)d_in[6];
    const float* W[3] = {(const float*)d_in[7], (const float*)d_in[10], (const float*)d_in[13]};
    const float* Rt[3] = {(const float*)d_in[8], (const float*)d_in[11], (const float*)d_in[14]};
    const float* Bi[3] = {(const float*)d_in[9], (const float*)d_in[12], (const float*)d_in[15]};
    const float* fc1w = (const float*)d_in[16];
    const float* fc1b = (const float*)d_in[17];
    const float* fc2w = (const float*)d_in[18];
    const float* fc2b = (const float*)d_in[19];
    float* out = (float*)d_out;
    const int* src = ei;
    const int* tgt = ei + NE;

    cudaFuncSetAttribute(k_gemm, cudaFuncAttributeMaxDynamicSharedMemorySize, GEMM_SMEM);

    // zero counts via memset node
    void* cl_ptr = nullptr;
    cudaGetSymbolAddress(&cl_ptr, g_cntlook);
    cudaMemsetAsync(cl_ptr, 0, (NRSEG + 256) * sizeof(int), 0);

    k_hist_h0<<<(NN * 32 + 64 + 255) / 256, 256>>>(tgt, etyp, x_op, x_cat, opemb, catemb,
                                                   W[0], Rt[0], W[1], Rt[1], W[2], Rt[2]);
    k_scan1<<<SC_NB, 1024>>>();
    k_scatter_goff<<<SGB, 256>>>(src, tgt, etyp, batch);

    // 3 RGCN layers, ping-pong hA/hB
    for (int l = 0; l < 3; ++l) {
        int inB = l & 1;
        k_agg<<<(NN * 32 + 255) / 256, 256>>>(inB);
        k_gemm<<<(NN + 127) / 128, 256, GEMM_SMEM>>>(inB, l, Bi[l], (l < 2) ? 1 : 0);
    }

    k_pool<<<dim3(GG, 4), 256>>>(1); // final h is in g_hB
    k_head<<<1, 64>>>(fc1w, fc1b, fc2w, fc2b, out);
}

// round 15
// speedup vs baseline: 1.3057x; 1.0133x over previous
#include <cuda_runtime.h>
#include <cuda_bf16.h>
#include <cstdint>

#define NN 200000
#define NE 4000000
#define RR 4
#define DD 64
#define NRSEG (NN*RR)
#define GG 64
#define CC 10
#define ZN NN                            // sentinel node -> zero row
#define NES (NE + 3*NRSEG)               // padded edge-list capacity
#define SC_NB ((NRSEG + 1023) / 1024)    // 782 scan blocks
#define SGB ((NE + 1023) / 1024)         // 3907 scatter blocks
#define SLICE ((NRSEG + SGB - 1) / SGB)  // 205 offsets finalized per block
#define NW 61440                         // 3*5*4096 weight elems

// ---------------- device scratch (no allocations allowed) ----------------
static __device__ __align__(16) int   g_cntlook[NRSEG + 256]; // true counts
static __device__ __align__(16) int   g_off[NRSEG];    // padded per-block partial
static __device__ __align__(16) int   g_off2[NRSEG];   // padded finalized exclusive
static __device__ __align__(16) int   g_bsum[1024];
static __device__ __align__(16) int   g_rank[NE];
static __device__ __align__(16) int   g_sorted[NES];
static __device__ __align__(16) int   g_goff[GG + 1];
static __device__ __align__(16) __nv_bfloat16 g_hA[(NN + 1) * DD];
static __device__ __align__(16) __nv_bfloat16 g_hB[(NN + 1) * DD];
static __device__ __align__(16) __nv_bfloat16 g_M[RR * NN * DD]; // [r][node][64]
static __device__ __align__(16) __nv_bfloat16 g_Wb[NW];          // [l][c][k][e]
static __device__ __align__(16) float g_pp[GG * 4 * DD];

__device__ __forceinline__ void cpa16(uint32_t dst, const void* src, int srcsize) {
    asm volatile("cp.async.ca.shared.global [%0], [%1], 16, %2;"
                 :: "r"(dst), "l"(src), "r"(srcsize));
}

// ---------------- fused: hist(+rank, int4 edges) + h0 + zero + weights -----
__global__ void k_hist_h0(const int* __restrict__ tgt, const int* __restrict__ et,
                          const int* __restrict__ xop, const int* __restrict__ xcat,
                          const float* __restrict__ opemb, const float* __restrict__ catemb,
                          const float* __restrict__ w1, const float* __restrict__ r1,
                          const float* __restrict__ w2, const float* __restrict__ r2,
                          const float* __restrict__ w3, const float* __restrict__ r3) {
    int i = blockIdx.x * blockDim.x + threadIdx.x;
    if (i < NE / 4) {   // 4 edges per thread, vectorized streams
        int4 t4 = ((const int4*)tgt)[i];
        int4 e4 = ((const int4*)et)[i];
        int4 r4;
        r4.x = atomicAdd(&g_cntlook[t4.x * RR + e4.x], 1);
        r4.y = atomicAdd(&g_cntlook[t4.y * RR + e4.y], 1);
        r4.z = atomicAdd(&g_cntlook[t4.z * RR + e4.z], 1);
        r4.w = atomicAdd(&g_cntlook[t4.w * RR + e4.w], 1);
        ((int4*)g_rank)[i] = r4;
        if (i < NW) { // weight conversion rides along
            int l = i / 20480, r = i % 20480, c = r / 4096, j = r % 4096;
            const float* w = (l == 0) ? w1 : (l == 1) ? w2 : w3;
            const float* rt = (l == 0) ? r1 : (l == 1) ? r2 : r3;
            float v = (c < 4) ? w[c * 4096 + j] : rt[j];
            g_Wb[i] = __float2bfloat16(v);
        }
    }
    if (i < NN * 32) {
        int n = i >> 5, j = i & 31;
        const float2* oe = (const float2*)opemb;
        const float2* ce = (const float2*)catemb;
        float2 a = oe[xop[n] * 32 + j];
        float2 b = ce[xcat[n] * 32 + j];
        ((__nv_bfloat162*)g_hA)[n * 32 + j] =
            __float22bfloat162_rn(make_float2(a.x + b.x, a.y + b.y));
    } else if (i < NN * 32 + 64) {
        int j = i - NN * 32;
        __nv_bfloat162 z = __float2bfloat162_rn(0.f);
        if (j < 32) ((__nv_bfloat162*)g_hA)[NN * 32 + j] = z;
        else        ((__nv_bfloat162*)g_hB)[NN * 32 + (j - 32)] = z;
    }
}

// ---------------- block-local exclusive scan over PADDED counts -----------
__global__ void k_scan1() {
    __shared__ int sh[1024];
    int t = threadIdx.x;
    int i = blockIdx.x * 1024 + t;
    int v = 0;
    if (i < NRSEG) v = (g_cntlook[i] + 3) & ~3;   // pad to multiple of 4
    sh[t] = v;
    __syncthreads();
    for (int s = 1; s < 1024; s <<= 1) {
        int add = (t >= s) ? sh[t - s] : 0;
        __syncthreads();
        sh[t] += add;
        __syncthreads();
    }
    if (i < NRSEG) g_off[i] = sh[t] - v;
    if (t == 1023) g_bsum[blockIdx.x] = sh[1023];
}

// ---------------- fused: bsum-prefix + finalize + pad-fill + scatter + goff
__global__ __launch_bounds__(256) void k_scatter_goff(const int* __restrict__ srcarr,
                                                      const int* __restrict__ tgt,
                                                      const int* __restrict__ et,
                                                      const int* __restrict__ batch) {
    __shared__ int pre[1024];
    __shared__ int wsum[8];
    int b = blockIdx.x, t = threadIdx.x;
    int x[4];
    int run = 0;
#pragma unroll
    for (int k = 0; k < 4; ++k) {
        int i = t * 4 + k;
        int v = (i < SC_NB) ? g_bsum[i] : 0;
        x[k] = run;
        run += v;
    }
    int lane = t & 31, wp = t >> 5;
    int inc = run;
#pragma unroll
    for (int d = 1; d < 32; d <<= 1) {
        int y = __shfl_up_sync(0xffffffffu, inc, d);
        if (lane >= d) inc += y;
    }
    if (lane == 31) wsum[wp] = inc;
    __syncthreads();
    if (wp == 0) {
        int ws = (lane < 8) ? wsum[lane] : 0;
#pragma unroll
        for (int d = 1; d < 8; d <<= 1) {
            int y = __shfl_up_sync(0xffffffffu, ws, d);
            if (lane >= d) ws += y;
        }
        if (lane < 8) wsum[lane] = ws;
    }
    __syncthreads();
    int excl = inc - run + (wp > 0 ? wsum[wp - 1] : 0);
#pragma unroll
    for (int k = 0; k < 4; ++k) pre[t * 4 + k] = excl + x[k];
    __syncthreads();

    // finalize slice of padded offsets + fill pad slots with sentinel ZN
    if (t < SLICE) {
        int i = b * SLICE + t;
        if (i < NRSEG) {
            int o = g_off[i] + pre[i >> 10];
            g_off2[i] = o;
            int c = g_cntlook[i];
            int pc = (c + 3) & ~3;
            for (int p = c; p < pc; ++p) g_sorted[o + p] = ZN;
        }
    }

    // atomic-free scatter, 4 edges/thread via int4 streams + batch boundaries
    {
        int gi = b * 256 + t;               // int4 index; 4 edges
        if (gi < NE / 4) {
            int4 t4 = ((const int4*)tgt)[gi];
            int4 e4 = ((const int4*)et)[gi];
            int4 s4 = ((const int4*)srcarr)[gi];
            int4 r4 = ((const int4*)g_rank)[gi];
            int s;
            s = t4.x * RR + e4.x; g_sorted[g_off[s] + pre[s >> 10] + r4.x] = s4.x;
            s = t4.y * RR + e4.y; g_sorted[g_off[s] + pre[s >> 10] + r4.y] = s4.y;
            s = t4.z * RR + e4.z; g_sorted[g_off[s] + pre[s >> 10] + r4.z] = s4.z;
            s = t4.w * RR + e4.w; g_sorted[g_off[s] + pre[s >> 10] + r4.w] = s4.w;
        }
#pragma unroll
        for (int k = 0; k < 4; ++k) {
            int e = gi * 4 + k;
            if (e < NN) {
                int bb = batch[e];
                if (e == 0) {
                    for (int g = 0; g <= bb; ++g) g_goff[g] = 0;
                } else {
                    int bp = batch[e - 1];
                    for (int g = bp + 1; g <= bb; ++g) g_goff[g] = e;
                }
                if (e == NN - 1) {
                    for (int g = bb + 1; g <= GG; ++g) g_goff[g] = NN;
                }
            }
        }
    }
}

// ---------------- per-(node,relation) mean aggregation v5 ------------------
__global__ __launch_bounds__(256) void k_agg(int inB) {
    int gw = (blockIdx.x * blockDim.x + threadIdx.x) >> 5;
    int lane = threadIdx.x & 31;
    if (gw >= NN) return;
    int q = lane & 7;
    int g = lane >> 3;
    const __nv_bfloat16* hin = inB ? g_hB : g_hA;

    int off_g = g_off2[gw * RR + g];      // 8-lane broadcast load
    int cnt_g = g_cntlook[gw * RR + g];   // 8-lane broadcast load
    int iters_g = (cnt_g + 3) >> 2;
    int im = iters_g;
    im = max(im, __shfl_xor_sync(0xffffffffu, im, 8));
    im = max(im, __shfl_xor_sync(0xffffffffu, im, 16));

    __nv_bfloat162 a0 = __float2bfloat162_rn(0.f);
    __nv_bfloat162 a1 = a0, a2 = a0, a3 = a0;

    const int4* ip = (const int4*)(g_sorted + off_g);  // off_g % 4 == 0
    const int4 zf = make_int4(ZN, ZN, ZN, ZN);
    int4 i4 = (0 < iters_g) ? ip[0] : zf;
    for (int it = 0; it < im; ++it) {
        int4 nxt = ((it + 1) < iters_g) ? ip[it + 1] : zf;
#pragma unroll
        for (int t = 0; t < 4; ++t) {
            int sn = (t == 0) ? i4.x : (t == 1) ? i4.y : (t == 2) ? i4.z : i4.w;
            uint4 v = *(const uint4*)(hin + sn * 64 + q * 8);
            a0 = __hadd2(a0, *(const __nv_bfloat162*)&v.x);
            a1 = __hadd2(a1, *(const __nv_bfloat162*)&v.y);
            a2 = __hadd2(a2, *(const __nv_bfloat162*)&v.z);
            a3 = __hadd2(a3, *(const __nv_bfloat162*)&v.w);
        }
        i4 = nxt;
    }

    float inv = (cnt_g > 0) ? (1.f / (float)cnt_g) : 0.f;
    __nv_bfloat162 o[4];
    float2 f;
    f = __bfloat1622float2(a0); o[0] = __float22bfloat162_rn(make_float2(f.x * inv, f.y * inv));
    f = __bfloat1622float2(a1); o[1] = __float22bfloat162_rn(make_float2(f.x * inv, f.y * inv));
    f = __bfloat1622float2(a2); o[2] = __float22bfloat162_rn(make_float2(f.x * inv, f.y * inv));
    f = __bfloat1622float2(a3); o[3] = __float22bfloat162_rn(make_float2(f.x * inv, f.y * inv));
    *(uint4*)(g_M + (g * NN + gw) * 64 + q * 8) = *(const uint4*)o;
}

// ---------------- tensor-core GEMM (R10: 256-node tile, 2-buf cp.async) ----
#define ASTR 72
#define A_ELEM (256 * ASTR)
#define B_ELEM (64 * ASTR)
#define GEMM_SMEM (2 * A_ELEM * 2 + 2 * B_ELEM * 2 + 256)
__global__ __launch_bounds__(256) void k_gemm(int inB, int l,
                                              const float* __restrict__ bias,
                                              int do_relu) {
    extern __shared__ __align__(16) unsigned char dsm[];
    __nv_bfloat16* As = (__nv_bfloat16*)dsm;
    __nv_bfloat16* Bs = (__nv_bfloat16*)(dsm + 2 * A_ELEM * 2);
    float* biass = (float*)(dsm + 2 * A_ELEM * 2 + 2 * B_ELEM * 2);

    const __nv_bfloat16* hin = inB ? g_hB : g_hA;
    __nv_bfloat16* hout = inB ? g_hA : g_hB;
    const __nv_bfloat16* wb = g_Wb + l * 20480;

    int tid = threadIdx.x;
    int lane = tid & 31;
    int wp = tid >> 5;
    int nbase = blockIdx.x * 256;

    if (tid < 64) biass[tid] = bias[tid];

    float d[2][4][2][4];
#pragma unroll
    for (int rg = 0; rg < 2; ++rg)
#pragma unroll
        for (int t = 0; t < 4; ++t)
#pragma unroll
            for (int s = 0; s < 2; ++s)
#pragma unroll
                for (int i = 0; i < 4; ++i) d[rg][t][s][i] = 0.f;

    uint32_t as_base = (uint32_t)__cvta_generic_to_shared(As);
    uint32_t bs_base = (uint32_t)__cvta_generic_to_shared(Bs);

    auto stage = [&](int c, int buf) {
#pragma unroll
        for (int it = 0; it < 2; ++it) {      // B: 64x64 bf16 = 512 x 16B
            int idx = it * 256 + tid;
            int kk = idx >> 3, e8 = idx & 7;
            uint32_t dst = bs_base + (buf * B_ELEM + kk * ASTR + e8 * 8) * 2;
            cpa16(dst, wb + c * 4096 + kk * 64 + e8 * 8, 16);
        }
#pragma unroll
        for (int it = 0; it < 8; ++it) {      // A: 256x64 bf16 = 2048 x 16B
            int idx = it * 256 + tid;
            int node = idx >> 3, k8 = idx & 7;
            int gn = nbase + node;
            int gs = gn < NN ? gn : NN - 1;
            const __nv_bfloat16* src = (c < 4) ? (g_M + (c * NN + gs) * 64 + k8 * 8)
                                               : (hin + gs * 64 + k8 * 8);
            uint32_t dst = as_base + (buf * A_ELEM + node * ASTR + k8 * 8) * 2;
            cpa16(dst, src, gn < NN ? 16 : 0);
        }
    };

    stage(0, 0);
    asm volatile("cp.async.commit_group;");

    for (int c = 0; c < 5; ++c) {
        int buf = c & 1;
        if (c < 4) {
            stage(c + 1, (c + 1) & 1);
            asm volatile("cp.async.commit_group;");
            asm volatile("cp.async.wait_group 1;");
        } else {
            asm volatile("cp.async.wait_group 0;");
        }
        __syncthreads();

        uint32_t ab = as_base + buf * A_ELEM * 2;
        uint32_t bb = bs_base + buf * B_ELEM * 2;
#pragma unroll
        for (int ks = 0; ks < 4; ++ks) {
            uint32_t a[2][4];
#pragma unroll
            for (int rg = 0; rg < 2; ++rg) {
                uint32_t aaddr = ab +
                    ((wp * 32 + rg * 16 + (lane & 15)) * ASTR + ks * 16 + ((lane >> 4) << 3)) * 2;
                asm volatile(
                    "ldmatrix.sync.aligned.m8n8.x4.shared.b16 {%0,%1,%2,%3}, [%4];"
                    : "=r"(a[rg][0]), "=r"(a[rg][1]), "=r"(a[rg][2]), "=r"(a[rg][3])
                    : "r"(aaddr));
            }
#pragma unroll
            for (int t = 0; t < 4; ++t) {
                uint32_t b0, b1, b2, b3;
                uint32_t baddr = bb +
                    ((ks * 16 + (lane & 15)) * ASTR + t * 16 + ((lane >> 4) << 3)) * 2;
                asm volatile(
                    "ldmatrix.sync.aligned.m8n8.x4.trans.shared.b16 {%0,%1,%2,%3}, [%4];"
                    : "=r"(b0), "=r"(b1), "=r"(b2), "=r"(b3) : "r"(baddr));
#pragma unroll
                for (int rg = 0; rg < 2; ++rg) {
                    asm volatile(
                        "mma.sync.aligned.m16n8k16.row.col.f32.bf16.bf16.f32 "
                        "{%0,%1,%2,%3}, {%4,%5,%6,%7}, {%8,%9}, {%0,%1,%2,%3};"
                        : "+f"(d[rg][t][0][0]), "+f"(d[rg][t][0][1]),
                          "+f"(d[rg][t][0][2]), "+f"(d[rg][t][0][3])
                        : "r"(a[rg][0]), "r"(a[rg][1]), "r"(a[rg][2]), "r"(a[rg][3]),
                          "r"(b0), "r"(b1));
                    asm volatile(
                        "mma.sync.aligned.m16n8k16.row.col.f32.bf16.bf16.f32 "
                        "{%0,%1,%2,%3}, {%4,%5,%6,%7}, {%8,%9}, {%0,%1,%2,%3};"
                        : "+f"(d[rg][t][1][0]), "+f"(d[rg][t][1][1]),
                          "+f"(d[rg][t][1][2]), "+f"(d[rg][t][1][3])
                        : "r"(a[rg][0]), "r"(a[rg][1]), "r"(a[rg][2]), "r"(a[rg][3]),
                          "r"(b2), "r"(b3));
                }
            }
        }
        __syncthreads();
    }

    // epilogue: bias + relu, bf16 store
    __nv_bfloat162* hout2 = (__nv_bfloat162*)hout;
#pragma unroll
    for (int rg = 0; rg < 2; ++rg) {
        int r0 = nbase + wp * 32 + rg * 16 + (lane >> 2);
        int r1 = r0 + 8;
#pragma unroll
        for (int t = 0; t < 4; ++t) {
#pragma unroll
            for (int s = 0; s < 2; ++s) {
                int n0 = t * 16 + s * 8 + (lane & 3) * 2;
                float bx = biass[n0], by = biass[n0 + 1];
                float v0 = d[rg][t][s][0] + bx, v1 = d[rg][t][s][1] + by;
                float v2 = d[rg][t][s][2] + bx, v3 = d[rg][t][s][3] + by;
                if (do_relu) {
                    v0 = fmaxf(v0, 0.f); v1 = fmaxf(v1, 0.f);
                    v2 = fmaxf(v2, 0.f); v3 = fmaxf(v3, 0.f);
                }
                if (r0 < NN)
                    hout2[r0 * 32 + n0 / 2] = __float22bfloat162_rn(make_float2(v0, v1));
                if (r1 < NN)
                    hout2[r1 * 32 + n0 / 2] = __float22bfloat162_rn(make_float2(v2, v3));
            }
        }
    }
}

// ---------------- pooling: (graph, quarter) partial sums -------------------
__global__ void k_pool(int inB) {
    const __nv_bfloat16* h = inB ? g_hB : g_hA;
    int g = blockIdx.x, qt = blockIdx.y;
    int st = g_goff[g], en = g_goff[g + 1];
    int len = en - st;
    int n0 = st + (len * qt) / 4;
    int n1 = st + (len * (qt + 1)) / 4;
    int d = threadIdx.x & 63;
    int y = threadIdx.x >> 6;
    float acc = 0.f;
    for (int n = n0 + y; n < n1; n += 4) acc += __bfloat162float(h[n * DD + d]);
    __shared__ float red[4][64];
    red[y][d] = acc;
    __syncthreads();
    if (y == 0)
        g_pp[(g * 4 + qt) * DD + d] = red[0][d] + red[1][d] + red[2][d] + red[3][d];
}

// ---------------- MLP head + log_softmax ------------------------------------
__global__ void k_head(const float* __restrict__ fc1w, const float* __restrict__ fc1b,
                       const float* __restrict__ fc2w, const float* __restrict__ fc2b,
                       float* __restrict__ out) {
    __shared__ float w1s[DD * DD];
    __shared__ float w2s[DD * CC];
    __shared__ float b1s[DD];
    __shared__ float b2s[CC];
    int t = threadIdx.x; // 64 threads
    for (int i = t; i < DD * DD; i += 64) w1s[i] = fc1w[i];
    for (int i = t; i < DD * CC; i += 64) w2s[i] = fc2w[i];
    if (t < DD) b1s[t] = fc1b[t];
    if (t < CC) b2s[t] = fc2b[t];
    __syncthreads();
    int g = t;
    int cnt = g_goff[g + 1] - g_goff[g];
    float inv = 1.f / (float)(cnt > 0 ? cnt : 1);
    float p[DD];
#pragma unroll
    for (int d = 0; d < DD; ++d)
        p[d] = (g_pp[(g * 4 + 0) * DD + d] + g_pp[(g * 4 + 1) * DD + d] +
                g_pp[(g * 4 + 2) * DD + d] + g_pp[(g * 4 + 3) * DD + d]) * inv;
    float t1[DD];
    for (int e = 0; e < DD; ++e) {
        float a = b1s[e];
#pragma unroll
        for (int d = 0; d < DD; ++d) a += p[d] * w1s[d * DD + e];
        t1[e] = fmaxf(a, 0.f);
    }
    float lg[CC];
    for (int c = 0; c < CC; ++c) {
        float a = b2s[c];
#pragma unroll
        for (int e = 0; e < DD; ++e) a += t1[e] * w2s[e * CC + c];
        lg[c] = a;
    }
    float m = lg[0];
    for (int c = 1; c < CC; ++c) m = fmaxf(m, lg[c]);
    float s = 0.f;
    for (int c = 0; c < CC; ++c) s += expf(lg[c] - m);
    float ls = logf(s);
    for (int c = 0; c < CC; ++c) out[g * CC + c] = lg[c] - m - ls;
}

// ---------------- launch --------------------------------------------------
extern "C" void kernel_launch(void* const* d_in, const int* in_sizes, int n_in,
                              void* d_out, int out_size) {
    const int* x_op = (const int*)d_in[0];
    const int* x_cat = (const int*)d_in[1];
    const int* ei = (const int*)d_in[2];
    const int* etyp = (const int*)d_in[3];
    const int* batch = (const int*)d_in[4];
    const float* opemb = (const float*)d_in[5];
    const float* catemb = (const float*)d_in[6];
    const float* W[3] = {(const float*)d_in[7], (const float*)d_in[10], (const float*)d_in[13]};
    const float* Rt[3] = {(const float*)d_in[8], (const float*)d_in[11], (const float*)d_in[14]};
    const float* Bi[3] = {(const float*)d_in[9], (const float*)d_in[12], (const float*)d_in[15]};
    const float* fc1w = (const float*)d_in[16];
    const float* fc1b = (const float*)d_in[17];
    const float* fc2w = (const float*)d_in[18];
    const float* fc2b = (const float*)d_in[19];
    float* out = (float*)d_out;
    const int* src = ei;
    const int* tgt = ei + NE;

    cudaFuncSetAttribute(k_gemm, cudaFuncAttributeMaxDynamicSharedMemorySize, GEMM_SMEM);

    // zero counts via memset node
    void* cl_ptr = nullptr;
    cudaGetSymbolAddress(&cl_ptr, g_cntlook);
    cudaMemsetAsync(cl_ptr, 0, (NRSEG + 256) * sizeof(int), 0);

    k_hist_h0<<<(NN * 32 + 64 + 255) / 256, 256>>>(tgt, etyp, x_op, x_cat, opemb, catemb,
                                                   W[0], Rt[0], W[1], Rt[1], W[2], Rt[2]);
    k_scan1<<<SC_NB, 1024>>>();
    k_scatter_goff<<<SGB, 256>>>(src, tgt, etyp, batch);

    // 3 RGCN layers, ping-pong hA/hB
    for (int l = 0; l < 3; ++l) {
        int inB = l & 1;
        k_agg<<<(NN * 32 + 255) / 256, 256>>>(inB);
        k_gemm<<<(NN + 255) / 256, 256, GEMM_SMEM>>>(inB, l, Bi[l], (l < 2) ? 1 : 0);
    }

    k_pool<<<dim3(GG, 4), 256>>>(1); // final h is in g_hB
    k_head<<<1, 64>>>(fc1w, fc1b, fc2w, fc2b, out);
}

// round 16
// speedup vs baseline: 1.3677x; 1.0475x over previous
#include <cuda_runtime.h>
#include <cuda_bf16.h>
#include <cstdint>

#define NN 200000
#define NE 4000000
#define RR 4
#define DD 64
#define NRSEG (NN*RR)
#define GG 64
#define CC 10
#define ZN NN                            // sentinel node -> zero row
#define NES (NE + 3*NRSEG)               // padded edge-list capacity
#define SC_NB ((NRSEG + 1023) / 1024)    // 782 scan blocks
#define SGB ((NE + 1023) / 1024)         // 3907 scatter blocks
#define SLICE ((NRSEG + SGB - 1) / SGB)  // 205 offsets finalized per block
#define NW 61440                         // 3*5*4096 weight elems

// ---------------- device scratch (no allocations allowed) ----------------
static __device__ __align__(16) int   g_cntlook[NRSEG + 256]; // true counts
static __device__ __align__(16) int   g_off[NRSEG];    // padded per-block partial
static __device__ __align__(16) int   g_off2[NRSEG];   // padded finalized exclusive
static __device__ __align__(16) int   g_bsum[1024];
static __device__ __align__(16) int   g_rank[NE];
static __device__ __align__(16) int   g_sorted[NES];
static __device__ __align__(16) int   g_goff[GG + 1];
static __device__ __align__(16) __nv_bfloat16 g_hA[(NN + 1) * DD];
static __device__ __align__(16) __nv_bfloat16 g_hB[(NN + 1) * DD];
static __device__ __align__(16) __nv_bfloat16 g_M[RR * NN * DD]; // [r][node][64]
static __device__ __align__(16) __nv_bfloat16 g_Wb[NW];          // [l][c][k][e]
static __device__ __align__(16) float g_pp[GG * 4 * DD];

__device__ __forceinline__ void cpa16(uint32_t dst, const void* src, int srcsize) {
    asm volatile("cp.async.ca.shared.global [%0], [%1], 16, %2;"
                 :: "r"(dst), "l"(src), "r"(srcsize));
}

// ---------------- fused: hist(+rank) + h0 + zero rows + weight conversion --
__global__ void k_hist_h0(const int* __restrict__ tgt, const int* __restrict__ et,
                          const int* __restrict__ xop, const int* __restrict__ xcat,
                          const float* __restrict__ opemb, const float* __restrict__ catemb,
                          const float* __restrict__ w1, const float* __restrict__ r1,
                          const float* __restrict__ w2, const float* __restrict__ r2,
                          const float* __restrict__ w3, const float* __restrict__ r3) {
    int i = blockIdx.x * blockDim.x + threadIdx.x;
    if (i < NE) {
        int s = tgt[i] * RR + et[i];
        g_rank[i] = atomicAdd(&g_cntlook[s], 1);
        if (i < NW) { // weight conversion rides along (NW << NE)
            int l = i / 20480, r = i % 20480, c = r / 4096, j = r % 4096;
            const float* w = (l == 0) ? w1 : (l == 1) ? w2 : w3;
            const float* rt = (l == 0) ? r1 : (l == 1) ? r2 : r3;
            float v = (c < 4) ? w[c * 4096 + j] : rt[j];
            g_Wb[i] = __float2bfloat16(v);
        }
    }
    if (i < NN * 32) {
        int n = i >> 5, j = i & 31;
        const float2* oe = (const float2*)opemb;
        const float2* ce = (const float2*)catemb;
        float2 a = oe[xop[n] * 32 + j];
        float2 b = ce[xcat[n] * 32 + j];
        ((__nv_bfloat162*)g_hA)[n * 32 + j] =
            __float22bfloat162_rn(make_float2(a.x + b.x, a.y + b.y));
    } else if (i < NN * 32 + 64) {
        int j = i - NN * 32;
        __nv_bfloat162 z = __float2bfloat162_rn(0.f);
        if (j < 32) ((__nv_bfloat162*)g_hA)[NN * 32 + j] = z;
        else        ((__nv_bfloat162*)g_hB)[NN * 32 + (j - 32)] = z;
    }
}

// ---------------- block-local exclusive scan over PADDED counts -----------
__global__ void k_scan1() {
    __shared__ int sh[1024];
    int t = threadIdx.x;
    int i = blockIdx.x * 1024 + t;
    int v = 0;
    if (i < NRSEG) v = (g_cntlook[i] + 3) & ~3;   // pad to multiple of 4
    sh[t] = v;
    __syncthreads();
    for (int s = 1; s < 1024; s <<= 1) {
        int add = (t >= s) ? sh[t - s] : 0;
        __syncthreads();
        sh[t] += add;
        __syncthreads();
    }
    if (i < NRSEG) g_off[i] = sh[t] - v;
    if (t == 1023) g_bsum[blockIdx.x] = sh[1023];
}

// ---------------- fused: bsum-prefix + finalize + pad-fill + scatter + goff
__global__ __launch_bounds__(256) void k_scatter_goff(const int* __restrict__ srcarr,
                                                      const int* __restrict__ tgt,
                                                      const int* __restrict__ et,
                                                      const int* __restrict__ batch) {
    __shared__ int pre[1024];
    __shared__ int wsum[8];
    int b = blockIdx.x, t = threadIdx.x;
    int x[4];
    int run = 0;
#pragma unroll
    for (int k = 0; k < 4; ++k) {
        int i = t * 4 + k;
        int v = (i < SC_NB) ? g_bsum[i] : 0;
        x[k] = run;
        run += v;
    }
    int lane = t & 31, wp = t >> 5;
    int inc = run;
#pragma unroll
    for (int d = 1; d < 32; d <<= 1) {
        int y = __shfl_up_sync(0xffffffffu, inc, d);
        if (lane >= d) inc += y;
    }
    if (lane == 31) wsum[wp] = inc;
    __syncthreads();
    if (wp == 0) {
        int ws = (lane < 8) ? wsum[lane] : 0;
#pragma unroll
        for (int d = 1; d < 8; d <<= 1) {
            int y = __shfl_up_sync(0xffffffffu, ws, d);
            if (lane >= d) ws += y;
        }
        if (lane < 8) wsum[lane] = ws;
    }
    __syncthreads();
    int excl = inc - run + (wp > 0 ? wsum[wp - 1] : 0);
#pragma unroll
    for (int k = 0; k < 4; ++k) pre[t * 4 + k] = excl + x[k];
    __syncthreads();

    // finalize slice of padded offsets + fill pad slots with sentinel ZN
    if (t < SLICE) {
        int i = b * SLICE + t;
        if (i < NRSEG) {
            int o = g_off[i] + pre[i >> 10];
            g_off2[i] = o;
            int c = g_cntlook[i];
            int pc = (c + 3) & ~3;
            for (int p = c; p < pc; ++p) g_sorted[o + p] = ZN;
        }
    }

    // atomic-free scatter + batch boundaries
#pragma unroll
    for (int k = 0; k < 4; ++k) {
        int e = b * 1024 + k * 256 + t;
        if (e < NE) {
            int s = tgt[e] * RR + et[e];
            g_sorted[g_off[s] + pre[s >> 10] + g_rank[e]] = srcarr[e];
        }
        if (e < NN) {
            int bb = batch[e];
            if (e == 0) {
                for (int g = 0; g <= bb; ++g) g_goff[g] = 0;
            } else {
                int bp = batch[e - 1];
                for (int g = bp + 1; g <= bb; ++g) g_goff[g] = e;
            }
            if (e == NN - 1) {
                for (int g = bb + 1; g <= GG; ++g) g_goff[g] = NN;
            }
        }
    }
}

// ---------------- per-(node,relation) mean aggregation v6 ------------------
// Warp = 2 nodes (2w, 2w+1); 4 groups of 8 lanes own one relation each for
// BOTH nodes. Two interleaved independent gather chains -> 8 outstanding
// LDG.128 per iteration (2x MLP vs v5). Sentinel-padded segments, off%4==0.
__global__ __launch_bounds__(256) void k_agg(int inB) {
    int w = (blockIdx.x * blockDim.x + threadIdx.x) >> 5;
    int lane = threadIdx.x & 31;
    if (w >= NN / 2) return;
    int n0 = w * 2, n1 = n0 + 1;
    int q = lane & 7;
    int g = lane >> 3;
    const __nv_bfloat16* hin = inB ? g_hB : g_hA;

    int sA = n0 * RR + g, sB = n1 * RR + g;
    int offA = g_off2[sA], cntA = g_cntlook[sA];
    int offB = g_off2[sB], cntB = g_cntlook[sB];
    int itA = (cntA + 3) >> 2, itB = (cntB + 3) >> 2;
    int im = max(itA, itB);
    im = max(im, __shfl_xor_sync(0xffffffffu, im, 8));
    im = max(im, __shfl_xor_sync(0xffffffffu, im, 16));

    __nv_bfloat162 z2 = __float2bfloat162_rn(0.f);
    __nv_bfloat162 aA0 = z2, aA1 = z2, aA2 = z2, aA3 = z2;
    __nv_bfloat162 aB0 = z2, aB1 = z2, aB2 = z2, aB3 = z2;

    const int4* ipA = (const int4*)(g_sorted + offA);
    const int4* ipB = (const int4*)(g_sorted + offB);
    const int4 zf = make_int4(ZN, ZN, ZN, ZN);
    int4 iA = (0 < itA) ? ipA[0] : zf;
    int4 iB = (0 < itB) ? ipB[0] : zf;
    for (int it = 0; it < im; ++it) {
        int4 nA = ((it + 1) < itA) ? ipA[it + 1] : zf;
        int4 nB = ((it + 1) < itB) ? ipB[it + 1] : zf;
#pragma unroll
        for (int t = 0; t < 4; ++t) {
            int sa = (t == 0) ? iA.x : (t == 1) ? iA.y : (t == 2) ? iA.z : iA.w;
            int sb = (t == 0) ? iB.x : (t == 1) ? iB.y : (t == 2) ? iB.z : iB.w;
            uint4 va = *(const uint4*)(hin + sa * 64 + q * 8);
            uint4 vb = *(const uint4*)(hin + sb * 64 + q * 8);
            aA0 = __hadd2(aA0, *(const __nv_bfloat162*)&va.x);
            aA1 = __hadd2(aA1, *(const __nv_bfloat162*)&va.y);
            aA2 = __hadd2(aA2, *(const __nv_bfloat162*)&va.z);
            aA3 = __hadd2(aA3, *(const __nv_bfloat162*)&va.w);
            aB0 = __hadd2(aB0, *(const __nv_bfloat162*)&vb.x);
            aB1 = __hadd2(aB1, *(const __nv_bfloat162*)&vb.y);
            aB2 = __hadd2(aB2, *(const __nv_bfloat162*)&vb.z);
            aB3 = __hadd2(aB3, *(const __nv_bfloat162*)&vb.w);
        }
        iA = nA;
        iB = nB;
    }

    float invA = (cntA > 0) ? (1.f / (float)cntA) : 0.f;
    float invB = (cntB > 0) ? (1.f / (float)cntB) : 0.f;
    __nv_bfloat162 oA[4], oB[4];
    float2 f;
    f = __bfloat1622float2(aA0); oA[0] = __float22bfloat162_rn(make_float2(f.x * invA, f.y * invA));
    f = __bfloat1622float2(aA1); oA[1] = __float22bfloat162_rn(make_float2(f.x * invA, f.y * invA));
    f = __bfloat1622float2(aA2); oA[2] = __float22bfloat162_rn(make_float2(f.x * invA, f.y * invA));
    f = __bfloat1622float2(aA3); oA[3] = __float22bfloat162_rn(make_float2(f.x * invA, f.y * invA));
    f = __bfloat1622float2(aB0); oB[0] = __float22bfloat162_rn(make_float2(f.x * invB, f.y * invB));
    f = __bfloat1622float2(aB1); oB[1] = __float22bfloat162_rn(make_float2(f.x * invB, f.y * invB));
    f = __bfloat1622float2(aB2); oB[2] = __float22bfloat162_rn(make_float2(f.x * invB, f.y * invB));
    f = __bfloat1622float2(aB3); oB[3] = __float22bfloat162_rn(make_float2(f.x * invB, f.y * invB));
    *(uint4*)(g_M + (g * NN + n0) * 64 + q * 8) = *(const uint4*)oA;
    *(uint4*)(g_M + (g * NN + n1) * 64 + q * 8) = *(const uint4*)oB;
}

// ---------------- tensor-core GEMM (R10: 256-node tile, 2-buf cp.async) ----
#define ASTR 72
#define A_ELEM (256 * ASTR)
#define B_ELEM (64 * ASTR)
#define GEMM_SMEM (2 * A_ELEM * 2 + 2 * B_ELEM * 2 + 256)
__global__ __launch_bounds__(256) void k_gemm(int inB, int l,
                                              const float* __restrict__ bias,
                                              int do_relu) {
    extern __shared__ __align__(16) unsigned char dsm[];
    __nv_bfloat16* As = (__nv_bfloat16*)dsm;
    __nv_bfloat16* Bs = (__nv_bfloat16*)(dsm + 2 * A_ELEM * 2);
    float* biass = (float*)(dsm + 2 * A_ELEM * 2 + 2 * B_ELEM * 2);

    const __nv_bfloat16* hin = inB ? g_hB : g_hA;
    __nv_bfloat16* hout = inB ? g_hA : g_hB;
    const __nv_bfloat16* wb = g_Wb + l * 20480;

    int tid = threadIdx.x;
    int lane = tid & 31;
    int wp = tid >> 5;
    int nbase = blockIdx.x * 256;

    if (tid < 64) biass[tid] = bias[tid];

    float d[2][4][2][4];
#pragma unroll
    for (int rg = 0; rg < 2; ++rg)
#pragma unroll
        for (int t = 0; t < 4; ++t)
#pragma unroll
            for (int s = 0; s < 2; ++s)
#pragma unroll
                for (int i = 0; i < 4; ++i) d[rg][t][s][i] = 0.f;

    uint32_t as_base = (uint32_t)__cvta_generic_to_shared(As);
    uint32_t bs_base = (uint32_t)__cvta_generic_to_shared(Bs);

    auto stage = [&](int c, int buf) {
#pragma unroll
        for (int it = 0; it < 2; ++it) {      // B: 64x64 bf16 = 512 x 16B
            int idx = it * 256 + tid;
            int kk = idx >> 3, e8 = idx & 7;
            uint32_t dst = bs_base + (buf * B_ELEM + kk * ASTR + e8 * 8) * 2;
            cpa16(dst, wb + c * 4096 + kk * 64 + e8 * 8, 16);
        }
#pragma unroll
        for (int it = 0; it < 8; ++it) {      // A: 256x64 bf16 = 2048 x 16B
            int idx = it * 256 + tid;
            int node = idx >> 3, k8 = idx & 7;
            int gn = nbase + node;
            int gs = gn < NN ? gn : NN - 1;
            const __nv_bfloat16* src = (c < 4) ? (g_M + (c * NN + gs) * 64 + k8 * 8)
                                               : (hin + gs * 64 + k8 * 8);
            uint32_t dst = as_base + (buf * A_ELEM + node * ASTR + k8 * 8) * 2;
            cpa16(dst, src, gn < NN ? 16 : 0);
        }
    };

    stage(0, 0);
    asm volatile("cp.async.commit_group;");

    for (int c = 0; c < 5; ++c) {
        int buf = c & 1;
        if (c < 4) {
            stage(c + 1, (c + 1) & 1);
            asm volatile("cp.async.commit_group;");
            asm volatile("cp.async.wait_group 1;");
        } else {
            asm volatile("cp.async.wait_group 0;");
        }
        __syncthreads();

        uint32_t ab = as_base + buf * A_ELEM * 2;
        uint32_t bb = bs_base + buf * B_ELEM * 2;
#pragma unroll
        for (int ks = 0; ks < 4; ++ks) {
            uint32_t a[2][4];
#pragma unroll
            for (int rg = 0; rg < 2; ++rg) {
                uint32_t aaddr = ab +
                    ((wp * 32 + rg * 16 + (lane & 15)) * ASTR + ks * 16 + ((lane >> 4) << 3)) * 2;
                asm volatile(
                    "ldmatrix.sync.aligned.m8n8.x4.shared.b16 {%0,%1,%2,%3}, [%4];"
                    : "=r"(a[rg][0]), "=r"(a[rg][1]), "=r"(a[rg][2]), "=r"(a[rg][3])
                    : "r"(aaddr));
            }
#pragma unroll
            for (int t = 0; t < 4; ++t) {
                uint32_t b0, b1, b2, b3;
                uint32_t baddr = bb +
                    ((ks * 16 + (lane & 15)) * ASTR + t * 16 + ((lane >> 4) << 3)) * 2;
                asm volatile(
                    "ldmatrix.sync.aligned.m8n8.x4.trans.shared.b16 {%0,%1,%2,%3}, [%4];"
                    : "=r"(b0), "=r"(b1), "=r"(b2), "=r"(b3) : "r"(baddr));
#pragma unroll
                for (int rg = 0; rg < 2; ++rg) {
                    asm volatile(
                        "mma.sync.aligned.m16n8k16.row.col.f32.bf16.bf16.f32 "
                        "{%0,%1,%2,%3}, {%4,%5,%6,%7}, {%8,%9}, {%0,%1,%2,%3};"
                        : "+f"(d[rg][t][0][0]), "+f"(d[rg][t][0][1]),
                          "+f"(d[rg][t][0][2]), "+f"(d[rg][t][0][3])
                        : "r"(a[rg][0]), "r"(a[rg][1]), "r"(a[rg][2]), "r"(a[rg][3]),
                          "r"(b0), "r"(b1));
                    asm volatile(
                        "mma.sync.aligned.m16n8k16.row.col.f32.bf16.bf16.f32 "
                        "{%0,%1,%2,%3}, {%4,%5,%6,%7}, {%8,%9}, {%0,%1,%2,%3};"
                        : "+f"(d[rg][t][1][0]), "+f"(d[rg][t][1][1]),
                          "+f"(d[rg][t][1][2]), "+f"(d[rg][t][1][3])
                        : "r"(a[rg][0]), "r"(a[rg][1]), "r"(a[rg][2]), "r"(a[rg][3]),
                          "r"(b2), "r"(b3));
                }
            }
        }
        __syncthreads();
    }

    // epilogue: bias + relu, bf16 store
    __nv_bfloat162* hout2 = (__nv_bfloat162*)hout;
#pragma unroll
    for (int rg = 0; rg < 2; ++rg) {
        int r0 = nbase + wp * 32 + rg * 16 + (lane >> 2);
        int r1 = r0 + 8;
#pragma unroll
        for (int t = 0; t < 4; ++t) {
#pragma unroll
            for (int s = 0; s < 2; ++s) {
                int n0 = t * 16 + s * 8 + (lane & 3) * 2;
                float bx = biass[n0], by = biass[n0 + 1];
                float v0 = d[rg][t][s][0] + bx, v1 = d[rg][t][s][1] + by;
                float v2 = d[rg][t][s][2] + bx, v3 = d[rg][t][s][3] + by;
                if (do_relu) {
                    v0 = fmaxf(v0, 0.f); v1 = fmaxf(v1, 0.f);
                    v2 = fmaxf(v2, 0.f); v3 = fmaxf(v3, 0.f);
                }
                if (r0 < NN)
                    hout2[r0 * 32 + n0 / 2] = __float22bfloat162_rn(make_float2(v0, v1));
                if (r1 < NN)
                    hout2[r1 * 32 + n0 / 2] = __float22bfloat162_rn(make_float2(v2, v3));
            }
        }
    }
}

// ---------------- pooling: (graph, quarter) partial sums -------------------
__global__ void k_pool(int inB) {
    const __nv_bfloat16* h = inB ? g_hB : g_hA;
    int g = blockIdx.x, qt = blockIdx.y;
    int st = g_goff[g], en = g_goff[g + 1];
    int len = en - st;
    int n0 = st + (len * qt) / 4;
    int n1 = st + (len * (qt + 1)) / 4;
    int d = threadIdx.x & 63;
    int y = threadIdx.x >> 6;
    float acc = 0.f;
    for (int n = n0 + y; n < n1; n += 4) acc += __bfloat162float(h[n * DD + d]);
    __shared__ float red[4][64];
    red[y][d] = acc;
    __syncthreads();
    if (y == 0)
        g_pp[(g * 4 + qt) * DD + d] = red[0][d] + red[1][d] + red[2][d] + red[3][d];
}

// ---------------- MLP head + log_softmax ------------------------------------
__global__ void k_head(const float* __restrict__ fc1w, const float* __restrict__ fc1b,
                       const float* __restrict__ fc2w, const float* __restrict__ fc2b,
                       float* __restrict__ out) {
    __shared__ float w1s[DD * DD];
    __shared__ float w2s[DD * CC];
    __shared__ float b1s[DD];
    __shared__ float b2s[CC];
    int t = threadIdx.x; // 64 threads
    for (int i = t; i < DD * DD; i += 64) w1s[i] = fc1w[i];
    for (int i = t; i < DD * CC; i += 64) w2s[i] = fc2w[i];
    if (t < DD) b1s[t] = fc1b[t];
    if (t < CC) b2s[t] = fc2b[t];
    __syncthreads();
    int g = t;
    int cnt = g_goff[g + 1] - g_goff[g];
    float inv = 1.f / (float)(cnt > 0 ? cnt : 1);
    float p[DD];
#pragma unroll
    for (int d = 0; d < DD; ++d)
        p[d] = (g_pp[(g * 4 + 0) * DD + d] + g_pp[(g * 4 + 1) * DD + d] +
                g_pp[(g * 4 + 2) * DD + d] + g_pp[(g * 4 + 3) * DD + d]) * inv;
    float t1[DD];
    for (int e = 0; e < DD; ++e) {
        float a = b1s[e];
#pragma unroll
        for (int d = 0; d < DD; ++d) a += p[d] * w1s[d * DD + e];
        t1[e] = fmaxf(a, 0.f);
    }
    float lg[CC];
    for (int c = 0; c < CC; ++c) {
        float a = b2s[c];
#pragma unroll
        for (int e = 0; e < DD; ++e) a += t1[e] * w2s[e * CC + c];
        lg[c] = a;
    }
    float m = lg[0];
    for (int c = 1; c < CC; ++c) m = fmaxf(m, lg[c]);
    float s = 0.f;
    for (int c = 0; c < CC; ++c) s += expf(lg[c] - m);
    float ls = logf(s);
    for (int c = 0; c < CC; ++c) out[g * CC + c] = lg[c] - m - ls;
}

// ---------------- launch --------------------------------------------------
extern "C" void kernel_launch(void* const* d_in, const int* in_sizes, int n_in,
                              void* d_out, int out_size) {
    const int* x_op = (const int*)d_in[0];
    const int* x_cat = (const int*)d_in[1];
    const int* ei = (const int*)d_in[2];
    const int* etyp = (const int*)d_in[3];
    const int* batch = (const int*)d_in[4];
    const float* opemb = (const float*)d_in[5];
    const float* catemb = (const float*)d_in[6];
    const float* W[3] = {(const float*)d_in[7], (const float*)d_in[10], (const float*)d_in[13]};
    const float* Rt[3] = {(const float*)d_in[8], (const float*)d_in[11], (const float*)d_in[14]};
    const float* Bi[3] = {(const float*)d_in[9], (const float*)d_in[12], (const float*)d_in[15]};
    const float* fc1w = (const float*)d_in[16];
    const float* fc1b = (const float*)d_in[17];
    const float* fc2w = (const float*)d_in[18];
    const float* fc2b = (const float*)d_in[19];
    float* out = (float*)d_out;
    const int* src = ei;
    const int* tgt = ei + NE;

    cudaFuncSetAttribute(k_gemm, cudaFuncAttributeMaxDynamicSharedMemorySize, GEMM_SMEM);

    // zero counts via memset node
    void* cl_ptr = nullptr;
    cudaGetSymbolAddress(&cl_ptr, g_cntlook);
    cudaMemsetAsync(cl_ptr, 0, (NRSEG + 256) * sizeof(int), 0);

    k_hist_h0<<<(NN * 32 + 64 + 255) / 256, 256>>>(tgt, etyp, x_op, x_cat, opemb, catemb,
                                                   W[0], Rt[0], W[1], Rt[1], W[2], Rt[2]);
    k_scan1<<<SC_NB, 1024>>>();
    k_scatter_goff<<<SGB, 256>>>(src, tgt, etyp, batch);

    // 3 RGCN layers, ping-pong hA/hB
    for (int l = 0; l < 3; ++l) {
        int inB = l & 1;
        k_agg<<<((NN / 2) * 32 + 255) / 256, 256>>>(inB);
        k_gemm<<<(NN + 255) / 256, 256, GEMM_SMEM>>>(inB, l, Bi[l], (l < 2) ? 1 : 0);
    }

    k_pool<<<dim3(GG, 4), 256>>>(1); // final h is in g_hB
    k_head<<<1, 64>>>(fc1w, fc1b, fc2w, fc2b, out);
}

// round 17
// speedup vs baseline: 1.3679x; 1.0002x over previous
#include <cuda_runtime.h>
#include <cuda_bf16.h>
#include <cstdint>

#define NN 200000
#define NE 4000000
#define RR 4
#define DD 64
#define NRSEG (NN*RR)
#define GG 64
#define CC 10
#define ZN NN                            // sentinel node -> zero row
#define NES (NE + 3*NRSEG)               // padded edge-list capacity
#define SC_NB ((NRSEG + 1023) / 1024)    // 782 scan blocks
#define SGB ((NE + 1023) / 1024)         // 3907 scatter blocks
#define SLICE ((NRSEG + SGB - 1) / SGB)  // 205 offsets finalized per block
#define NW 61440                         // 3*5*4096 weight elems

// ---------------- device scratch (no allocations allowed) ----------------
static __device__ __align__(16) int   g_cntlook[NRSEG + 256]; // true counts
static __device__ __align__(16) int   g_off[NRSEG];    // padded per-block partial
static __device__ __align__(16) int   g_off2[NRSEG];   // padded finalized exclusive
static __device__ __align__(16) int   g_bsum[1024];
static __device__ __align__(16) int   g_rank[NE];
static __device__ __align__(16) int   g_sorted[NES];
static __device__ __align__(16) int   g_goff[GG + 1];
static __device__ __align__(16) __nv_bfloat16 g_hA[(NN + 1) * DD];
static __device__ __align__(16) __nv_bfloat16 g_hB[(NN + 1) * DD];
static __device__ __align__(16) __nv_bfloat16 g_M[RR * NN * DD]; // [r][node][64]
static __device__ __align__(16) __nv_bfloat16 g_Wb[NW];          // [l][c][k][e]
static __device__ __align__(16) float g_pp[GG * 4 * DD];

__device__ __forceinline__ void cpa16(uint32_t dst, const void* src, int srcsize) {
    asm volatile("cp.async.ca.shared.global [%0], [%1], 16, %2;"
                 :: "r"(dst), "l"(src), "r"(srcsize));
}

// ---------------- fused: hist(+rank) + h0 + zero rows + weight conversion --
__global__ void k_hist_h0(const int* __restrict__ tgt, const int* __restrict__ et,
                          const int* __restrict__ xop, const int* __restrict__ xcat,
                          const float* __restrict__ opemb, const float* __restrict__ catemb,
                          const float* __restrict__ w1, const float* __restrict__ r1,
                          const float* __restrict__ w2, const float* __restrict__ r2,
                          const float* __restrict__ w3, const float* __restrict__ r3) {
    int i = blockIdx.x * blockDim.x + threadIdx.x;
    if (i < NE) {
        int s = tgt[i] * RR + et[i];
        g_rank[i] = atomicAdd(&g_cntlook[s], 1);
        if (i < NW) { // weight conversion rides along (NW << NE)
            int l = i / 20480, r = i % 20480, c = r / 4096, j = r % 4096;
            const float* w = (l == 0) ? w1 : (l == 1) ? w2 : w3;
            const float* rt = (l == 0) ? r1 : (l == 1) ? r2 : r3;
            float v = (c < 4) ? w[c * 4096 + j] : rt[j];
            g_Wb[i] = __float2bfloat16(v);
        }
    }
    if (i < NN * 32) {
        int n = i >> 5, j = i & 31;
        const float2* oe = (const float2*)opemb;
        const float2* ce = (const float2*)catemb;
        float2 a = oe[xop[n] * 32 + j];
        float2 b = ce[xcat[n] * 32 + j];
        ((__nv_bfloat162*)g_hA)[n * 32 + j] =
            __float22bfloat162_rn(make_float2(a.x + b.x, a.y + b.y));
    } else if (i < NN * 32 + 64) {
        int j = i - NN * 32;
        __nv_bfloat162 z = __float2bfloat162_rn(0.f);
        if (j < 32) ((__nv_bfloat162*)g_hA)[NN * 32 + j] = z;
        else        ((__nv_bfloat162*)g_hB)[NN * 32 + (j - 32)] = z;
    }
}

// ---------------- block-local exclusive scan over PADDED counts -----------
__global__ void k_scan1() {
    __shared__ int sh[1024];
    int t = threadIdx.x;
    int i = blockIdx.x * 1024 + t;
    int v = 0;
    if (i < NRSEG) v = (g_cntlook[i] + 3) & ~3;   // pad to multiple of 4
    sh[t] = v;
    __syncthreads();
    for (int s = 1; s < 1024; s <<= 1) {
        int add = (t >= s) ? sh[t - s] : 0;
        __syncthreads();
        sh[t] += add;
        __syncthreads();
    }
    if (i < NRSEG) g_off[i] = sh[t] - v;
    if (t == 1023) g_bsum[blockIdx.x] = sh[1023];
}

// ---------------- one-block exclusive scan of block sums (in place) -------
__global__ void k_scan2() {
    __shared__ int sh[1024];
    int t = threadIdx.x;
    int v = (t < SC_NB) ? g_bsum[t] : 0;
    sh[t] = v;
    __syncthreads();
    for (int s = 1; s < 1024; s <<= 1) {
        int add = (t >= s) ? sh[t - s] : 0;
        __syncthreads();
        sh[t] += add;
        __syncthreads();
    }
    if (t < SC_NB) g_bsum[t] = sh[t] - v;   // exclusive
}

// ---------------- fused: finalize + pad-fill + scatter + goff -------------
// g_bsum already holds the exclusive prefix; per-edge just add bsum[s>>10].
__global__ __launch_bounds__(256) void k_scatter_goff(const int* __restrict__ srcarr,
                                                      const int* __restrict__ tgt,
                                                      const int* __restrict__ et,
                                                      const int* __restrict__ batch) {
    int b = blockIdx.x, t = threadIdx.x;

    // finalize slice of padded offsets + fill pad slots with sentinel ZN
    if (t < SLICE) {
        int i = b * SLICE + t;
        if (i < NRSEG) {
            int o = g_off[i] + g_bsum[i >> 10];
            g_off2[i] = o;
            int c = g_cntlook[i];
            int pc = (c + 3) & ~3;
            for (int p = c; p < pc; ++p) g_sorted[o + p] = ZN;
        }
    }

    // atomic-free scatter + batch boundaries
#pragma unroll
    for (int k = 0; k < 4; ++k) {
        int e = b * 1024 + k * 256 + t;
        if (e < NE) {
            int s = tgt[e] * RR + et[e];
            g_sorted[g_off[s] + g_bsum[s >> 10] + g_rank[e]] = srcarr[e];
        }
        if (e < NN) {
            int bb = batch[e];
            if (e == 0) {
                for (int g = 0; g <= bb; ++g) g_goff[g] = 0;
            } else {
                int bp = batch[e - 1];
                for (int g = bp + 1; g <= bb; ++g) g_goff[g] = e;
            }
            if (e == NN - 1) {
                for (int g = bb + 1; g <= GG; ++g) g_goff[g] = NN;
            }
        }
    }
}

// ---------------- per-(node,relation) mean aggregation v6 ------------------
// Warp = 2 nodes (2w, 2w+1); 4 groups of 8 lanes own one relation each for
// BOTH nodes. Two interleaved independent gather chains -> 8 outstanding
// LDG.128 per iteration. Sentinel-padded segments, off%4==0.
__global__ __launch_bounds__(256) void k_agg(int inB) {
    int w = (blockIdx.x * blockDim.x + threadIdx.x) >> 5;
    int lane = threadIdx.x & 31;
    if (w >= NN / 2) return;
    int n0 = w * 2, n1 = n0 + 1;
    int q = lane & 7;
    int g = lane >> 3;
    const __nv_bfloat16* hin = inB ? g_hB : g_hA;

    int sA = n0 * RR + g, sB = n1 * RR + g;
    int offA = g_off2[sA], cntA = g_cntlook[sA];
    int offB = g_off2[sB], cntB = g_cntlook[sB];
    int itA = (cntA + 3) >> 2, itB = (cntB + 3) >> 2;
    int im = max(itA, itB);
    im = max(im, __shfl_xor_sync(0xffffffffu, im, 8));
    im = max(im, __shfl_xor_sync(0xffffffffu, im, 16));

    __nv_bfloat162 z2 = __float2bfloat162_rn(0.f);
    __nv_bfloat162 aA0 = z2, aA1 = z2, aA2 = z2, aA3 = z2;
    __nv_bfloat162 aB0 = z2, aB1 = z2, aB2 = z2, aB3 = z2;

    const int4* ipA = (const int4*)(g_sorted + offA);
    const int4* ipB = (const int4*)(g_sorted + offB);
    const int4 zf = make_int4(ZN, ZN, ZN, ZN);
    int4 iA = (0 < itA) ? ipA[0] : zf;
    int4 iB = (0 < itB) ? ipB[0] : zf;
    for (int it = 0; it < im; ++it) {
        int4 nA = ((it + 1) < itA) ? ipA[it + 1] : zf;
        int4 nB = ((it + 1) < itB) ? ipB[it + 1] : zf;
#pragma unroll
        for (int t = 0; t < 4; ++t) {
            int sa = (t == 0) ? iA.x : (t == 1) ? iA.y : (t == 2) ? iA.z : iA.w;
            int sb = (t == 0) ? iB.x : (t == 1) ? iB.y : (t == 2) ? iB.z : iB.w;
            uint4 va = *(const uint4*)(hin + sa * 64 + q * 8);
            uint4 vb = *(const uint4*)(hin + sb * 64 + q * 8);
            aA0 = __hadd2(aA0, *(const __nv_bfloat162*)&va.x);
            aA1 = __hadd2(aA1, *(const __nv_bfloat162*)&va.y);
            aA2 = __hadd2(aA2, *(const __nv_bfloat162*)&va.z);
            aA3 = __hadd2(aA3, *(const __nv_bfloat162*)&va.w);
            aB0 = __hadd2(aB0, *(const __nv_bfloat162*)&vb.x);
            aB1 = __hadd2(aB1, *(const __nv_bfloat162*)&vb.y);
            aB2 = __hadd2(aB2, *(const __nv_bfloat162*)&vb.z);
            aB3 = __hadd2(aB3, *(const __nv_bfloat162*)&vb.w);
        }
        iA = nA;
        iB = nB;
    }

    float invA = (cntA > 0) ? (1.f / (float)cntA) : 0.f;
    float invB = (cntB > 0) ? (1.f / (float)cntB) : 0.f;
    __nv_bfloat162 oA[4], oB[4];
    float2 f;
    f = __bfloat1622float2(aA0); oA[0] = __float22bfloat162_rn(make_float2(f.x * invA, f.y * invA));
    f = __bfloat1622float2(aA1); oA[1] = __float22bfloat162_rn(make_float2(f.x * invA, f.y * invA));
    f = __bfloat1622float2(aA2); oA[2] = __float22bfloat162_rn(make_float2(f.x * invA, f.y * invA));
    f = __bfloat1622float2(aA3); oA[3] = __float22bfloat162_rn(make_float2(f.x * invA, f.y * invA));
    f = __bfloat1622float2(aB0); oB[0] = __float22bfloat162_rn(make_float2(f.x * invB, f.y * invB));
    f = __bfloat1622float2(aB1); oB[1] = __float22bfloat162_rn(make_float2(f.x * invB, f.y * invB));
    f = __bfloat1622float2(aB2); oB[2] = __float22bfloat162_rn(make_float2(f.x * invB, f.y * invB));
    f = __bfloat1622float2(aB3); oB[3] = __float22bfloat162_rn(make_float2(f.x * invB, f.y * invB));
    *(uint4*)(g_M + (g * NN + n0) * 64 + q * 8) = *(const uint4*)oA;
    *(uint4*)(g_M + (g * NN + n1) * 64 + q * 8) = *(const uint4*)oB;
}

// ---------------- tensor-core GEMM (R10: 256-node tile, 2-buf cp.async) ----
#define ASTR 72
#define A_ELEM (256 * ASTR)
#define B_ELEM (64 * ASTR)
#define GEMM_SMEM (2 * A_ELEM * 2 + 2 * B_ELEM * 2 + 256)
__global__ __launch_bounds__(256) void k_gemm(int inB, int l,
                                              const float* __restrict__ bias,
                                              int do_relu) {
    extern __shared__ __align__(16) unsigned char dsm[];
    __nv_bfloat16* As = (__nv_bfloat16*)dsm;
    __nv_bfloat16* Bs = (__nv_bfloat16*)(dsm + 2 * A_ELEM * 2);
    float* biass = (float*)(dsm + 2 * A_ELEM * 2 + 2 * B_ELEM * 2);

    const __nv_bfloat16* hin = inB ? g_hB : g_hA;
    __nv_bfloat16* hout = inB ? g_hA : g_hB;
    const __nv_bfloat16* wb = g_Wb + l * 20480;

    int tid = threadIdx.x;
    int lane = tid & 31;
    int wp = tid >> 5;
    int nbase = blockIdx.x * 256;

    if (tid < 64) biass[tid] = bias[tid];

    float d[2][4][2][4];
#pragma unroll
    for (int rg = 0; rg < 2; ++rg)
#pragma unroll
        for (int t = 0; t < 4; ++t)
#pragma unroll
            for (int s = 0; s < 2; ++s)
#pragma unroll
                for (int i = 0; i < 4; ++i) d[rg][t][s][i] = 0.f;

    uint32_t as_base = (uint32_t)__cvta_generic_to_shared(As);
    uint32_t bs_base = (uint32_t)__cvta_generic_to_shared(Bs);

    auto stage = [&](int c, int buf) {
#pragma unroll
        for (int it = 0; it < 2; ++it) {      // B: 64x64 bf16 = 512 x 16B
            int idx = it * 256 + tid;
            int kk = idx >> 3, e8 = idx & 7;
            uint32_t dst = bs_base + (buf * B_ELEM + kk * ASTR + e8 * 8) * 2;
            cpa16(dst, wb + c * 4096 + kk * 64 + e8 * 8, 16);
        }
#pragma unroll
        for (int it = 0; it < 8; ++it) {      // A: 256x64 bf16 = 2048 x 16B
            int idx = it * 256 + tid;
            int node = idx >> 3, k8 = idx & 7;
            int gn = nbase + node;
            int gs = gn < NN ? gn : NN - 1;
            const __nv_bfloat16* src = (c < 4) ? (g_M + (c * NN + gs) * 64 + k8 * 8)
                                               : (hin + gs * 64 + k8 * 8);
            uint32_t dst = as_base + (buf * A_ELEM + node * ASTR + k8 * 8) * 2;
            cpa16(dst, src, gn < NN ? 16 : 0);
        }
    };

    stage(0, 0);
    asm volatile("cp.async.commit_group;");

    for (int c = 0; c < 5; ++c) {
        int buf = c & 1;
        if (c < 4) {
            stage(c + 1, (c + 1) & 1);
            asm volatile("cp.async.commit_group;");
            asm volatile("cp.async.wait_group 1;");
        } else {
            asm volatile("cp.async.wait_group 0;");
        }
        __syncthreads();

        uint32_t ab = as_base + buf * A_ELEM * 2;
        uint32_t bb = bs_base + buf * B_ELEM * 2;
#pragma unroll
        for (int ks = 0; ks < 4; ++ks) {
            uint32_t a[2][4];
#pragma unroll
            for (int rg = 0; rg < 2; ++rg) {
                uint32_t aaddr = ab +
                    ((wp * 32 + rg * 16 + (lane & 15)) * ASTR + ks * 16 + ((lane >> 4) << 3)) * 2;
                asm volatile(
                    "ldmatrix.sync.aligned.m8n8.x4.shared.b16 {%0,%1,%2,%3}, [%4];"
                    : "=r"(a[rg][0]), "=r"(a[rg][1]), "=r"(a[rg][2]), "=r"(a[rg][3])
                    : "r"(aaddr));
            }
#pragma unroll
            for (int t = 0; t < 4; ++t) {
                uint32_t b0, b1, b2, b3;
                uint32_t baddr = bb +
                    ((ks * 16 + (lane & 15)) * ASTR + t * 16 + ((lane >> 4) << 3)) * 2;
                asm volatile(
                    "ldmatrix.sync.aligned.m8n8.x4.trans.shared.b16 {%0,%1,%2,%3}, [%4];"
                    : "=r"(b0), "=r"(b1), "=r"(b2), "=r"(b3) : "r"(baddr));
#pragma unroll
                for (int rg = 0; rg < 2; ++rg) {
                    asm volatile(
                        "mma.sync.aligned.m16n8k16.row.col.f32.bf16.bf16.f32 "
                        "{%0,%1,%2,%3}, {%4,%5,%6,%7}, {%8,%9}, {%0,%1,%2,%3};"
                        : "+f"(d[rg][t][0][0]), "+f"(d[rg][t][0][1]),
                          "+f"(d[rg][t][0][2]), "+f"(d[rg][t][0][3])
                        : "r"(a[rg][0]), "r"(a[rg][1]), "r"(a[rg][2]), "r"(a[rg][3]),
                          "r"(b0), "r"(b1));
                    asm volatile(
                        "mma.sync.aligned.m16n8k16.row.col.f32.bf16.bf16.f32 "
                        "{%0,%1,%2,%3}, {%4,%5,%6,%7}, {%8,%9}, {%0,%1,%2,%3};"
                        : "+f"(d[rg][t][1][0]), "+f"(d[rg][t][1][1]),
                          "+f"(d[rg][t][1][2]), "+f"(d[rg][t][1][3])
                        : "r"(a[rg][0]), "r"(a[rg][1]), "r"(a[rg][2]), "r"(a[rg][3]),
                          "r"(b2), "r"(b3));
                }
            }
        }
        __syncthreads();
    }

    // epilogue: bias + relu, bf16 store
    __nv_bfloat162* hout2 = (__nv_bfloat162*)hout;
#pragma unroll
    for (int rg = 0; rg < 2; ++rg) {
        int r0 = nbase + wp * 32 + rg * 16 + (lane >> 2);
        int r1 = r0 + 8;
#pragma unroll
        for (int t = 0; t < 4; ++t) {
#pragma unroll
            for (int s = 0; s < 2; ++s) {
                int n0 = t * 16 + s * 8 + (lane & 3) * 2;
                float bx = biass[n0], by = biass[n0 + 1];
                float v0 = d[rg][t][s][0] + bx, v1 = d[rg][t][s][1] + by;
                float v2 = d[rg][t][s][2] + bx, v3 = d[rg][t][s][3] + by;
                if (do_relu) {
                    v0 = fmaxf(v0, 0.f); v1 = fmaxf(v1, 0.f);
                    v2 = fmaxf(v2, 0.f); v3 = fmaxf(v3, 0.f);
                }
                if (r0 < NN)
                    hout2[r0 * 32 + n0 / 2] = __float22bfloat162_rn(make_float2(v0, v1));
                if (r1 < NN)
                    hout2[r1 * 32 + n0 / 2] = __float22bfloat162_rn(make_float2(v2, v3));
            }
        }
    }
}

// ---------------- pooling: (graph, quarter) partial sums -------------------
__global__ void k_pool(int inB) {
    const __nv_bfloat16* h = inB ? g_hB : g_hA;
    int g = blockIdx.x, qt = blockIdx.y;
    int st = g_goff[g], en = g_goff[g + 1];
    int len = en - st;
    int n0 = st + (len * qt) / 4;
    int n1 = st + (len * (qt + 1)) / 4;
    int d = threadIdx.x & 63;
    int y = threadIdx.x >> 6;
    float acc = 0.f;
    for (int n = n0 + y; n < n1; n += 4) acc += __bfloat162float(h[n * DD + d]);
    __shared__ float red[4][64];
    red[y][d] = acc;
    __syncthreads();
    if (y == 0)
        g_pp[(g * 4 + qt) * DD + d] = red[0][d] + red[1][d] + red[2][d] + red[3][d];
}

// ---------------- MLP head + log_softmax ------------------------------------
__global__ void k_head(const float* __restrict__ fc1w, const float* __restrict__ fc1b,
                       const float* __restrict__ fc2w, const float* __restrict__ fc2b,
                       float* __restrict__ out) {
    __shared__ float w1s[DD * DD];
    __shared__ float w2s[DD * CC];
    __shared__ float b1s[DD];
    __shared__ float b2s[CC];
    int t = threadIdx.x; // 64 threads
    for (int i = t; i < DD * DD; i += 64) w1s[i] = fc1w[i];
    for (int i = t; i < DD * CC; i += 64) w2s[i] = fc2w[i];
    if (t < DD) b1s[t] = fc1b[t];
    if (t < CC) b2s[t] = fc2b[t];
    __syncthreads();
    int g = t;
    int cnt = g_goff[g + 1] - g_goff[g];
    float inv = 1.f / (float)(cnt > 0 ? cnt : 1);
    float p[DD];
#pragma unroll
    for (int d = 0; d < DD; ++d)
        p[d] = (g_pp[(g * 4 + 0) * DD + d] + g_pp[(g * 4 + 1) * DD + d] +
                g_pp[(g * 4 + 2) * DD + d] + g_pp[(g * 4 + 3) * DD + d]) * inv;
    float t1[DD];
    for (int e = 0; e < DD; ++e) {
        float a = b1s[e];
#pragma unroll
        for (int d = 0; d < DD; ++d) a += p[d] * w1s[d * DD + e];
        t1[e] = fmaxf(a, 0.f);
    }
    float lg[CC];
    for (int c = 0; c < CC; ++c) {
        float a = b2s[c];
#pragma unroll
        for (int e = 0; e < DD; ++e) a += t1[e] * w2s[e * CC + c];
        lg[c] = a;
    }
    float m = lg[0];
    for (int c = 1; c < CC; ++c) m = fmaxf(m, lg[c]);
    float s = 0.f;
    for (int c = 0; c < CC; ++c) s += expf(lg[c] - m);
    float ls = logf(s);
    for (int c = 0; c < CC; ++c) out[g * CC + c] = lg[c] - m - ls;
}

// ---------------- launch --------------------------------------------------
extern "C" void kernel_launch(void* const* d_in, const int* in_sizes, int n_in,
                              void* d_out, int out_size) {
    const int* x_op = (const int*)d_in[0];
    const int* x_cat = (const int*)d_in[1];
    const int* ei = (const int*)d_in[2];
    const int* etyp = (const int*)d_in[3];
    const int* batch = (const int*)d_in[4];
    const float* opemb = (const float*)d_in[5];
    const float* catemb = (const float*)d_in[6];
    const float* W[3] = {(const float*)d_in[7], (const float*)d_in[10], (const float*)d_in[13]};
    const float* Rt[3] = {(const float*)d_in[8], (const float*)d_in[11], (const float*)d_in[14]};
    const float* Bi[3] = {(const float*)d_in[9], (const float*)d_in[12], (const float*)d_in[15]};
    const float* fc1w = (const float*)d_in[16];
    const float* fc1b = (const float*)d_in[17];
    const float* fc2w = (const float*)d_in[18];
    const float* fc2b = (const float*)d_in[19];
    float* out = (float*)d_out;
    const int* src = ei;
    const int* tgt = ei + NE;

    cudaFuncSetAttribute(k_gemm, cudaFuncAttributeMaxDynamicSharedMemorySize, GEMM_SMEM);

    // zero counts via memset node
    void* cl_ptr = nullptr;
    cudaGetSymbolAddress(&cl_ptr, g_cntlook);
    cudaMemsetAsync(cl_ptr, 0, (NRSEG + 256) * sizeof(int), 0);

    k_hist_h0<<<(NN * 32 + 64 + 255) / 256, 256>>>(tgt, etyp, x_op, x_cat, opemb, catemb,
                                                   W[0], Rt[0], W[1], Rt[1], W[2], Rt[2]);
    k_scan1<<<SC_NB, 1024>>>();
    k_scan2<<<1, 1024>>>();
    k_scatter_goff<<<SGB, 256>>>(src, tgt, etyp, batch);

    // 3 RGCN layers, ping-pong hA/hB
    for (int l = 0; l < 3; ++l) {
        int inB = l & 1;
        k_agg<<<((NN / 2) * 32 + 255) / 256, 256>>>(inB);
        k_gemm<<<(NN + 255) / 256, 256, GEMM_SMEM>>>(inB, l, Bi[l], (l < 2) ? 1 : 0);
    }

    k_pool<<<dim3(GG, 4), 256>>>(1); // final h is in g_hB
    k_head<<<1, 64>>>(fc1w, fc1b, fc2w, fc2b, out);
}